// round 1
// baseline (speedup 1.0000x reference)
#include <cuda_runtime.h>
#include <cuda_bf16.h>
#include <cstdint>

// Problem shape (fixed by the reference)
#define BATCH 16
#define SEQ   2048
#define DIM   512

// Scratch: attention matrix P [B, N, N] fp32 = 268 MB, plus inverse norms.
// __device__ globals are the sanctioned no-alloc scratch mechanism.
__device__ float g_scores[(size_t)BATCH * SEQ * SEQ];
__device__ float g_invnorm[BATCH * SEQ];

// ---------------------------------------------------------------------------
// Kernel 1: inverse L2 norms. One warp per row (512 elems).
// ---------------------------------------------------------------------------
__global__ void k_norms(const float* __restrict__ x, float* __restrict__ invn) {
    int row  = blockIdx.x * 8 + (threadIdx.x >> 5);   // 8 warps/block
    int lane = threadIdx.x & 31;
    const float* p = x + (size_t)row * DIM;
    float s = 0.f;
#pragma unroll
    for (int k = lane; k < DIM; k += 32) {
        float t = p[k];
        s = fmaf(t, t, s);
    }
#pragma unroll
    for (int o = 16; o > 0; o >>= 1)
        s += __shfl_xor_sync(0xffffffffu, s, o);
    if (lane == 0) invn[row] = rsqrtf(s);
}

// ---------------------------------------------------------------------------
// Kernel 2: S = (X Xᵀ) scaled by invnorm_i * invnorm_j.   NT SGEMM,
// M = N = 2048, K = 512, batched over 16. 128x128x16 tile, 8x8 per thread.
// ---------------------------------------------------------------------------
#define BM 128
#define BN 128
#define BK 16

__global__ __launch_bounds__(256, 1)
void k_gemm_scores(const float* __restrict__ x,
                   const float* __restrict__ invn,
                   float* __restrict__ S) {
    const int b = blockIdx.z;
    const float* X  = x + (size_t)b * SEQ * DIM;
    float*       Sb = S + (size_t)b * SEQ * SEQ;
    const int rowBase = blockIdx.y * BM;
    const int colBase = blockIdx.x * BN;

    __shared__ float As[BK][BM];
    __shared__ float Bs[BK][BN];

    const int tid = threadIdx.x;
    const int tx  = tid & 15;       // 0..15 -> 8 cols each
    const int ty  = tid >> 4;       // 0..15 -> 8 rows each

    // Load mapping: BM x BK tile = 128 rows * 4 float4/row = 512 float4 / 256 thr
    const int lr = tid >> 2;        // 0..63, rows lr and lr+64
    const int lc = (tid & 3) * 4;   // k-offset 0,4,8,12

    float acc[8][8];
#pragma unroll
    for (int i = 0; i < 8; i++)
#pragma unroll
        for (int j = 0; j < 8; j++) acc[i][j] = 0.f;

    for (int k0 = 0; k0 < DIM; k0 += BK) {
#pragma unroll
        for (int s = 0; s < 2; s++) {
            int r = lr + s * 64;
            float4 v = *(const float4*)(X + (size_t)(rowBase + r) * DIM + k0 + lc);
            As[lc + 0][r] = v.x; As[lc + 1][r] = v.y;
            As[lc + 2][r] = v.z; As[lc + 3][r] = v.w;
            float4 w = *(const float4*)(X + (size_t)(colBase + r) * DIM + k0 + lc);
            Bs[lc + 0][r] = w.x; Bs[lc + 1][r] = w.y;
            Bs[lc + 2][r] = w.z; Bs[lc + 3][r] = w.w;
        }
        __syncthreads();

#pragma unroll
        for (int kk = 0; kk < BK; kk++) {
            float a[8], bb[8];
#pragma unroll
            for (int i = 0; i < 8; i++) a[i]  = As[kk][ty * 8 + i];
#pragma unroll
            for (int j = 0; j < 8; j++) bb[j] = Bs[kk][tx * 8 + j];
#pragma unroll
            for (int i = 0; i < 8; i++)
#pragma unroll
                for (int j = 0; j < 8; j++)
                    acc[i][j] = fmaf(a[i], bb[j], acc[i][j]);
        }
        __syncthreads();
    }

    const float* invb = invn + b * SEQ;
    float ri[8], rj[8];
#pragma unroll
    for (int i = 0; i < 8; i++) ri[i] = invb[rowBase + ty * 8 + i];
#pragma unroll
    for (int j = 0; j < 8; j++) rj[j] = invb[colBase + tx * 8 + j];

#pragma unroll
    for (int i = 0; i < 8; i++) {
        size_t base = (size_t)(rowBase + ty * 8 + i) * SEQ + colBase + tx * 8;
        float4 o0, o1;
        o0.x = acc[i][0] * ri[i] * rj[0];
        o0.y = acc[i][1] * ri[i] * rj[1];
        o0.z = acc[i][2] * ri[i] * rj[2];
        o0.w = acc[i][3] * ri[i] * rj[3];
        o1.x = acc[i][4] * ri[i] * rj[4];
        o1.y = acc[i][5] * ri[i] * rj[5];
        o1.z = acc[i][6] * ri[i] * rj[6];
        o1.w = acc[i][7] * ri[i] * rj[7];
        *(float4*)(Sb + base)     = o0;
        *(float4*)(Sb + base + 4) = o1;
    }
}

// ---------------------------------------------------------------------------
// Kernel 3: in-place row softmax over the last dim (2048). One block per row.
// ---------------------------------------------------------------------------
__global__ __launch_bounds__(256)
void k_softmax(float* __restrict__ S) {
    float* r = S + (size_t)blockIdx.x * SEQ;
    const int tid = threadIdx.x;
    __shared__ float red[256];

    float v[8];
    float m = -1e30f;
#pragma unroll
    for (int i = 0; i < 8; i++) {
        v[i] = r[tid + i * 256];
        m = fmaxf(m, v[i]);
    }
    red[tid] = m;
    __syncthreads();
#pragma unroll
    for (int s = 128; s > 0; s >>= 1) {
        if (tid < s) red[tid] = fmaxf(red[tid], red[tid + s]);
        __syncthreads();
    }
    m = red[0];
    __syncthreads();

    float sum = 0.f;
#pragma unroll
    for (int i = 0; i < 8; i++) {
        v[i] = __expf(v[i] - m);
        sum += v[i];
    }
    red[tid] = sum;
    __syncthreads();
#pragma unroll
    for (int s = 128; s > 0; s >>= 1) {
        if (tid < s) red[tid] += red[tid + s];
        __syncthreads();
    }
    float inv = 1.f / red[0];
#pragma unroll
    for (int i = 0; i < 8; i++) r[tid + i * 256] = v[i] * inv;
}

// ---------------------------------------------------------------------------
// Kernel 4: O = P @ X.   NN SGEMM, M = 2048, N = 512, K = 2048, batched.
// ---------------------------------------------------------------------------
__global__ __launch_bounds__(256, 1)
void k_gemm_out(const float* __restrict__ P,
                const float* __restrict__ x,
                float* __restrict__ O) {
    const int b = blockIdx.z;
    const float* Pb = P + (size_t)b * SEQ * SEQ;
    const float* X  = x + (size_t)b * SEQ * DIM;
    float*       Ob = O + (size_t)b * SEQ * DIM;
    const int rowBase = blockIdx.y * BM;   // over SEQ
    const int colBase = blockIdx.x * BN;   // over DIM

    __shared__ float As[BK][BM];
    __shared__ float Bs[BK][BN];

    const int tid = threadIdx.x;
    const int tx  = tid & 15;
    const int ty  = tid >> 4;

    // A (P) load mapping: like above
    const int lr = tid >> 2;
    const int lc = (tid & 3) * 4;
    // B (X) load mapping: BK x BN = 16 rows * 32 float4/row = 512 float4 / 256 thr
    const int kr = tid >> 5;          // 0..7, rows kr and kr+8
    const int kc = (tid & 31) * 4;    // col offset 0..124

    float acc[8][8];
#pragma unroll
    for (int i = 0; i < 8; i++)
#pragma unroll
        for (int j = 0; j < 8; j++) acc[i][j] = 0.f;

    for (int k0 = 0; k0 < SEQ; k0 += BK) {
#pragma unroll
        for (int s = 0; s < 2; s++) {
            int r = lr + s * 64;
            float4 v = *(const float4*)(Pb + (size_t)(rowBase + r) * SEQ + k0 + lc);
            As[lc + 0][r] = v.x; As[lc + 1][r] = v.y;
            As[lc + 2][r] = v.z; As[lc + 3][r] = v.w;
        }
#pragma unroll
        for (int s = 0; s < 2; s++) {
            int kk = kr + s * 8;
            float4 w = *(const float4*)(X + (size_t)(k0 + kk) * DIM + colBase + kc);
            *(float4*)&Bs[kk][kc] = w;
        }
        __syncthreads();

#pragma unroll
        for (int kk = 0; kk < BK; kk++) {
            float a[8], bb[8];
#pragma unroll
            for (int i = 0; i < 8; i++) a[i]  = As[kk][ty * 8 + i];
#pragma unroll
            for (int j = 0; j < 8; j++) bb[j] = Bs[kk][tx * 8 + j];
#pragma unroll
            for (int i = 0; i < 8; i++)
#pragma unroll
                for (int j = 0; j < 8; j++)
                    acc[i][j] = fmaf(a[i], bb[j], acc[i][j]);
        }
        __syncthreads();
    }

#pragma unroll
    for (int i = 0; i < 8; i++) {
        size_t base = (size_t)(rowBase + ty * 8 + i) * DIM + colBase + tx * 8;
        float4 o0, o1;
        o0.x = acc[i][0]; o0.y = acc[i][1]; o0.z = acc[i][2]; o0.w = acc[i][3];
        o1.x = acc[i][4]; o1.y = acc[i][5]; o1.z = acc[i][6]; o1.w = acc[i][7];
        *(float4*)(Ob + base)     = o0;
        *(float4*)(Ob + base + 4) = o1;
    }
}

// ---------------------------------------------------------------------------
extern "C" void kernel_launch(void* const* d_in, const int* in_sizes, int n_in,
                              void* d_out, int out_size) {
    const float* x = (const float*)d_in[0];
    float* out = (float*)d_out;

    float* scores;
    float* invn;
    cudaGetSymbolAddress((void**)&scores, g_scores);
    cudaGetSymbolAddress((void**)&invn, g_invnorm);

    // 1) inverse norms: 16*2048 rows, 1 warp each, 8 warps/block
    k_norms<<<(BATCH * SEQ) / 8, 256>>>(x, invn);

    // 2) scaled Gram matrix S = X̂ X̂ᵀ
    k_gemm_scores<<<dim3(SEQ / BN, SEQ / BM, BATCH), 256>>>(x, invn, scores);

    // 3) row softmax (in-place)
    k_softmax<<<BATCH * SEQ, 256>>>(scores);

    // 4) O = P X
    k_gemm_out<<<dim3(DIM / BN, SEQ / BM, BATCH), 256>>>(scores, x, out);
}

// round 6
// speedup vs baseline: 2.4940x; 2.4940x over previous
#include <cuda_runtime.h>
#include <cstdint>

#define BATCH 16
#define SEQ   2048
#define DIM   512

// ---------------------------------------------------------------------------
// Scratch (device globals = sanctioned no-alloc scratch)
// ---------------------------------------------------------------------------
__device__ float g_scores[(size_t)BATCH * SEQ * SEQ];   // 268 MB (S, then P tf32-rounded)
__device__ float g_xn   [(size_t)BATCH * SEQ * DIM];    // normalized x, tf32-rounded
__device__ float g_xc   [(size_t)BATCH * SEQ * DIM];    // raw x, tf32-rounded

// ---------------------------------------------------------------------------
// Helpers (baseline PTX, sm_80+ -- safe for compute_103 target)
// ---------------------------------------------------------------------------
__device__ __forceinline__ uint32_t smem_u32(const void* p) {
    uint32_t a;
    asm("{ .reg .u64 t; cvta.to.shared.u64 t, %1; cvt.u32.u64 %0, t; }" : "=r"(a) : "l"(p));
    return a;
}
__device__ __forceinline__ float to_tf32(float f) {
    uint32_t u;
    asm("cvt.rna.tf32.f32 %0, %1;" : "=r"(u) : "f"(f));
    return __uint_as_float(u);
}
#define CP_ASYNC16(dst, src) \
    asm volatile("cp.async.cg.shared.global [%0], [%1], 16;" :: "r"(dst), "l"(src))
#define CP_COMMIT() asm volatile("cp.async.commit_group;" ::: "memory")
#define CP_WAIT(n)  asm volatile("cp.async.wait_group %0;" :: "n"(n) : "memory")

__device__ __forceinline__ void mma_tf32(float* c,
                                         uint32_t a0, uint32_t a1, uint32_t a2, uint32_t a3,
                                         uint32_t b0, uint32_t b1) {
    asm volatile(
        "mma.sync.aligned.m16n8k8.row.col.f32.tf32.tf32.f32 "
        "{%0,%1,%2,%3}, {%4,%5,%6,%7}, {%8,%9}, {%0,%1,%2,%3};"
        : "+f"(c[0]), "+f"(c[1]), "+f"(c[2]), "+f"(c[3])
        : "r"(a0), "r"(a1), "r"(a2), "r"(a3), "r"(b0), "r"(b1));
}

// ---------------------------------------------------------------------------
// Kernel 1: row L2-normalize; write xn = tf32(x/|x|) and xc = tf32(x).
// ---------------------------------------------------------------------------
__global__ __launch_bounds__(128)
void k_norm(const float* __restrict__ x, float* __restrict__ xn, float* __restrict__ xc) {
    const size_t row = blockIdx.x;
    const int tid = threadIdx.x;
    float4 v = *(const float4*)(x + row * DIM + tid * 4);
    float s = v.x * v.x + v.y * v.y + v.z * v.z + v.w * v.w;
#pragma unroll
    for (int o = 16; o > 0; o >>= 1) s += __shfl_xor_sync(0xffffffffu, s, o);
    __shared__ float red[4];
    if ((tid & 31) == 0) red[tid >> 5] = s;
    __syncthreads();
    float inv = rsqrtf(red[0] + red[1] + red[2] + red[3]);
    float4 n, c;
    n.x = to_tf32(v.x * inv); n.y = to_tf32(v.y * inv);
    n.z = to_tf32(v.z * inv); n.w = to_tf32(v.w * inv);
    c.x = to_tf32(v.x); c.y = to_tf32(v.y); c.z = to_tf32(v.z); c.w = to_tf32(v.w);
    *(float4*)(xn + row * DIM + tid * 4) = n;
    *(float4*)(xc + row * DIM + tid * 4) = c;
}

// ---------------------------------------------------------------------------
// Kernel 2: tf32 mma.sync GEMM.
//   BT=1 (NT): D[m][n] = sum_k A[m][k] * B[n][k]   (both K-major)
//   BT=0 (NN): D[m][n] = sum_k A[m][k] * B[k][n]
// Block tile 128x128, K-chunk 16, cp.async double-buffered, 256 threads,
// 8 warps (2x4), warp tile 64x32, mma m16n8k8. STATIC smem <= 48 KB,
// no cudaFuncSetAttribute needed.
// ---------------------------------------------------------------------------
#define AS_STAGE 2560       // 128 rows * 20 floats (pad 16->20, conflict-free frag loads)
#define BS_STAGE_NT 2560
#define BS_STAGE_NN 2176    // 16 rows * 136 floats (pad 128->136)

template <int BT, int K>
__global__ __launch_bounds__(256, 1)
void k_mma(const float* __restrict__ A, size_t sA, int lda,
           const float* __restrict__ B, size_t sB, int ldb,
           float* __restrict__ D, size_t sD, int ldd) {
    constexpr int BS_STAGE = BT ? BS_STAGE_NT : BS_STAGE_NN;
    __shared__ float smA[2 * AS_STAGE];
    __shared__ float smB[2 * BS_STAGE];
    const uint32_t smA_u = smem_u32(smA);
    const uint32_t smB_u = smem_u32(smB);

    const int tid  = threadIdx.x;
    const int lane = tid & 31;
    const int wid  = tid >> 5;
    const int wm   = wid >> 2;        // 0..1
    const int wn   = wid & 3;         // 0..3
    const int gid  = lane >> 2;       // 0..7
    const int tg   = lane & 3;        // 0..3
    const int b    = blockIdx.z;

    const float* Ab = A + (size_t)b * sA + (size_t)blockIdx.y * 128 * lda;
    const float* Bb = B + (size_t)b * sB +
                      (BT ? (size_t)blockIdx.x * 128 * ldb : (size_t)blockIdx.x * 128);

    constexpr int NC = K / 16;

    auto load_stage = [&](int buf, int k0) {
        // A tile: 128 rows x 16 floats = 512 float4 segs / 256 threads
#pragma unroll
        for (int i = 0; i < 2; i++) {
            int s = tid + i * 256;
            int r = s >> 2, c = (s & 3) * 4;
            uint32_t dst = smA_u + (uint32_t)(buf * AS_STAGE + r * 20 + c) * 4u;
            CP_ASYNC16(dst, Ab + (size_t)r * lda + k0 + c);
        }
        if (BT) {
            // B tile: 128 rows (n) x 16 floats (k)
#pragma unroll
            for (int i = 0; i < 2; i++) {
                int s = tid + i * 256;
                int r = s >> 2, c = (s & 3) * 4;
                uint32_t dst = smB_u + (uint32_t)(buf * BS_STAGE + r * 20 + c) * 4u;
                CP_ASYNC16(dst, Bb + (size_t)r * ldb + k0 + c);
            }
        } else {
            // B tile: 16 rows (k) x 128 floats (n)
#pragma unroll
            for (int i = 0; i < 2; i++) {
                int s = tid + i * 256;
                int r = s >> 5, c = (s & 31) * 4;
                uint32_t dst = smB_u + (uint32_t)(buf * BS_STAGE + r * 136 + c) * 4u;
                CP_ASYNC16(dst, Bb + (size_t)(k0 + r) * ldb + c);
            }
        }
        CP_COMMIT();
    };

    float acc[4][4][4];
#pragma unroll
    for (int i = 0; i < 4; i++)
#pragma unroll
        for (int j = 0; j < 4; j++)
#pragma unroll
            for (int t = 0; t < 4; t++) acc[i][j][t] = 0.f;

    load_stage(0, 0);
    load_stage(1, 16);

    for (int c = 0; c < NC; ++c) {
        if (c + 1 < NC) CP_WAIT(1); else CP_WAIT(0);
        __syncthreads();

        const float* Ap = smA + (c & 1) * AS_STAGE;
        const float* Bp = smB + (c & 1) * BS_STAGE;
#pragma unroll
        for (int ks = 0; ks < 2; ks++) {
            uint32_t af[4][4];
#pragma unroll
            for (int i = 0; i < 4; i++) {
                int row = wm * 64 + i * 16;
                const float* base = Ap + (size_t)(row + gid) * 20 + ks * 8 + tg;
                af[i][0] = __float_as_uint(base[0]);
                af[i][1] = __float_as_uint(base[8 * 20]);
                af[i][2] = __float_as_uint(base[4]);
                af[i][3] = __float_as_uint(base[8 * 20 + 4]);
            }
            uint32_t bf[4][2];
#pragma unroll
            for (int j = 0; j < 4; j++) {
                int col = wn * 32 + j * 8;
                if (BT) {
                    const float* base = Bp + (size_t)(col + gid) * 20 + ks * 8 + tg;
                    bf[j][0] = __float_as_uint(base[0]);
                    bf[j][1] = __float_as_uint(base[4]);
                } else {
                    const float* base = Bp + (size_t)(ks * 8 + tg) * 136 + col + gid;
                    bf[j][0] = __float_as_uint(base[0]);
                    bf[j][1] = __float_as_uint(base[4 * 136]);
                }
            }
#pragma unroll
            for (int i = 0; i < 4; i++)
#pragma unroll
                for (int j = 0; j < 4; j++)
                    mma_tf32(acc[i][j], af[i][0], af[i][1], af[i][2], af[i][3],
                             bf[j][0], bf[j][1]);
        }
        __syncthreads();
        if (c + 2 < NC) load_stage(c & 1, (c + 2) * 16);
    }

    // epilogue
#pragma unroll
    for (int i = 0; i < 4; i++) {
#pragma unroll
        for (int j = 0; j < 4; j++) {
            int row = blockIdx.y * 128 + wm * 64 + i * 16 + gid;
            int col = blockIdx.x * 128 + wn * 32 + j * 8 + tg * 2;
            float* p = D + (size_t)b * sD + (size_t)row * ldd + col;
            *(float2*)p              = make_float2(acc[i][j][0], acc[i][j][1]);
            *(float2*)(p + 8 * ldd)  = make_float2(acc[i][j][2], acc[i][j][3]);
        }
    }
}

// ---------------------------------------------------------------------------
// Kernel 3: row softmax in-place, output tf32-rounded.
// ---------------------------------------------------------------------------
__global__ __launch_bounds__(256)
void k_softmax(float* __restrict__ S) {
    float* r = S + (size_t)blockIdx.x * SEQ;
    const int tid = threadIdx.x;
    __shared__ float red[256];

    float v[8];
    float m = -1e30f;
#pragma unroll
    for (int i = 0; i < 8; i++) { v[i] = r[tid + i * 256]; m = fmaxf(m, v[i]); }
    red[tid] = m; __syncthreads();
#pragma unroll
    for (int s = 128; s > 0; s >>= 1) {
        if (tid < s) red[tid] = fmaxf(red[tid], red[tid + s]);
        __syncthreads();
    }
    m = red[0]; __syncthreads();

    float sum = 0.f;
#pragma unroll
    for (int i = 0; i < 8; i++) { v[i] = __expf(v[i] - m); sum += v[i]; }
    red[tid] = sum; __syncthreads();
#pragma unroll
    for (int s = 128; s > 0; s >>= 1) {
        if (tid < s) red[tid] += red[tid + s];
        __syncthreads();
    }
    float inv = 1.f / red[0];
#pragma unroll
    for (int i = 0; i < 8; i++) r[tid + i * 256] = to_tf32(v[i] * inv);
}

// ---------------------------------------------------------------------------
extern "C" void kernel_launch(void* const* d_in, const int* in_sizes, int n_in,
                              void* d_out, int out_size) {
    const float* x = (const float*)d_in[0];
    float* out = (float*)d_out;

    float *scores, *xn, *xc;
    cudaGetSymbolAddress((void**)&scores, g_scores);
    cudaGetSymbolAddress((void**)&xn, g_xn);
    cudaGetSymbolAddress((void**)&xc, g_xc);

    // 1) normalize + tf32-round both operand copies
    k_norm<<<BATCH * SEQ, 128>>>(x, xn, xc);

    // 2) S = xn . xn^T   (NT, K = 512)
    k_mma<1, DIM><<<dim3(SEQ / 128, SEQ / 128, BATCH), 256>>>(
        xn, (size_t)SEQ * DIM, DIM,
        xn, (size_t)SEQ * DIM, DIM,
        scores, (size_t)SEQ * SEQ, SEQ);

    // 3) P = softmax(S), tf32-rounded in-place
    k_softmax<<<BATCH * SEQ, 256>>>(scores);

    // 4) O = P . X      (NN, K = 2048)
    k_mma<0, SEQ><<<dim3(DIM / 128, SEQ / 128, BATCH), 256>>>(
        scores, (size_t)SEQ * SEQ, SEQ,
        xc, (size_t)SEQ * DIM, DIM,
        out, (size_t)SEQ * DIM, DIM);
}

// round 7
// speedup vs baseline: 3.2310x; 1.2955x over previous
#include <cuda_runtime.h>
#include <cstdint>

#define BATCH 16
#define SEQ   2048
#define DIM   512

// ---------------------------------------------------------------------------
// Scratch (device globals = sanctioned no-alloc scratch)
// ---------------------------------------------------------------------------
__device__ float g_scores[(size_t)BATCH * SEQ * SEQ];   // 268 MB (S, then P tf32-rounded)
__device__ float g_xn   [(size_t)BATCH * SEQ * DIM];    // normalized x, tf32-rounded
__device__ float g_xc   [(size_t)BATCH * SEQ * DIM];    // raw x, tf32-rounded

// ---------------------------------------------------------------------------
// Helpers (baseline PTX, sm_80+ -- safe for compute_103 target)
// ---------------------------------------------------------------------------
__device__ __forceinline__ uint32_t smem_u32(const void* p) {
    uint32_t a;
    asm("{ .reg .u64 t; cvta.to.shared.u64 t, %1; cvt.u32.u64 %0, t; }" : "=r"(a) : "l"(p));
    return a;
}
__device__ __forceinline__ float to_tf32(float f) {
    uint32_t u;
    asm("cvt.rna.tf32.f32 %0, %1;" : "=r"(u) : "f"(f));
    return __uint_as_float(u);
}
#define CP_ASYNC16(dst, src) \
    asm volatile("cp.async.cg.shared.global [%0], [%1], 16;" :: "r"(dst), "l"(src))
#define CP_COMMIT() asm volatile("cp.async.commit_group;" ::: "memory")
#define CP_WAIT(n)  asm volatile("cp.async.wait_group %0;" :: "n"(n) : "memory")

__device__ __forceinline__ void mma_tf32(float* c,
                                         uint32_t a0, uint32_t a1, uint32_t a2, uint32_t a3,
                                         uint32_t b0, uint32_t b1) {
    asm volatile(
        "mma.sync.aligned.m16n8k8.row.col.f32.tf32.tf32.f32 "
        "{%0,%1,%2,%3}, {%4,%5,%6,%7}, {%8,%9}, {%0,%1,%2,%3};"
        : "+f"(c[0]), "+f"(c[1]), "+f"(c[2]), "+f"(c[3])
        : "r"(a0), "r"(a1), "r"(a2), "r"(a3), "r"(b0), "r"(b1));
}

// ---------------------------------------------------------------------------
// Kernel 1: row L2-normalize; write xn = tf32(x/|x|) and xc = tf32(x).
// ---------------------------------------------------------------------------
__global__ __launch_bounds__(128)
void k_norm(const float* __restrict__ x, float* __restrict__ xn, float* __restrict__ xc) {
    const size_t row = blockIdx.x;
    const int tid = threadIdx.x;
    float4 v = *(const float4*)(x + row * DIM + tid * 4);
    float s = v.x * v.x + v.y * v.y + v.z * v.z + v.w * v.w;
#pragma unroll
    for (int o = 16; o > 0; o >>= 1) s += __shfl_xor_sync(0xffffffffu, s, o);
    __shared__ float red[4];
    if ((tid & 31) == 0) red[tid >> 5] = s;
    __syncthreads();
    float inv = rsqrtf(red[0] + red[1] + red[2] + red[3]);
    float4 n, c;
    n.x = to_tf32(v.x * inv); n.y = to_tf32(v.y * inv);
    n.z = to_tf32(v.z * inv); n.w = to_tf32(v.w * inv);
    c.x = to_tf32(v.x); c.y = to_tf32(v.y); c.z = to_tf32(v.z); c.w = to_tf32(v.w);
    *(float4*)(xn + row * DIM + tid * 4) = n;
    *(float4*)(xc + row * DIM + tid * 4) = c;
}

// ---------------------------------------------------------------------------
// Kernel 2: tf32 mma.sync GEMM.
//   BT=1 (NT): D[m][n] = sum_k A[m][k] * B[n][k]   (both K-major)
//   BT=0 (NN): D[m][n] = sum_k A[m][k] * B[k][n]
// Block tile 128x128, K-chunk 16, cp.async double-buffered, 256 threads,
// 8 warps (2x4), warp tile 64x32, mma m16n8k8. STATIC smem <= 48 KB.
// __launch_bounds__(256, 2): cap regs at 128 -> 2 CTAs/SM (occupancy fix).
// ---------------------------------------------------------------------------
#define AS_STAGE 2560       // 128 rows * 20 floats (pad 16->20, conflict-free frag loads)
#define BS_STAGE_NT 2560
#define BS_STAGE_NN 2176    // 16 rows * 136 floats (pad 128->136)

template <int BT, int K>
__global__ __launch_bounds__(256, 2)
void k_mma(const float* __restrict__ A, size_t sA, int lda,
           const float* __restrict__ B, size_t sB, int ldb,
           float* __restrict__ D, size_t sD, int ldd) {
    constexpr int BS_STAGE = BT ? BS_STAGE_NT : BS_STAGE_NN;
    __shared__ float smA[2 * AS_STAGE];
    __shared__ float smB[2 * BS_STAGE];
    const uint32_t smA_u = smem_u32(smA);
    const uint32_t smB_u = smem_u32(smB);

    const int tid  = threadIdx.x;
    const int lane = tid & 31;
    const int wid  = tid >> 5;
    const int wm   = wid >> 2;        // 0..1
    const int wn   = wid & 3;         // 0..3
    const int gid  = lane >> 2;       // 0..7
    const int tg   = lane & 3;        // 0..3
    const int b    = blockIdx.z;

    const float* Ab = A + (size_t)b * sA + (size_t)blockIdx.y * 128 * lda;
    const float* Bb = B + (size_t)b * sB +
                      (BT ? (size_t)blockIdx.x * 128 * ldb : (size_t)blockIdx.x * 128);

    constexpr int NC = K / 16;

    auto load_stage = [&](int buf, int k0) {
        // A tile: 128 rows x 16 floats = 512 float4 segs / 256 threads
#pragma unroll
        for (int i = 0; i < 2; i++) {
            int s = tid + i * 256;
            int r = s >> 2, c = (s & 3) * 4;
            uint32_t dst = smA_u + (uint32_t)(buf * AS_STAGE + r * 20 + c) * 4u;
            CP_ASYNC16(dst, Ab + (size_t)r * lda + k0 + c);
        }
        if (BT) {
            // B tile: 128 rows (n) x 16 floats (k)
#pragma unroll
            for (int i = 0; i < 2; i++) {
                int s = tid + i * 256;
                int r = s >> 2, c = (s & 3) * 4;
                uint32_t dst = smB_u + (uint32_t)(buf * BS_STAGE + r * 20 + c) * 4u;
                CP_ASYNC16(dst, Bb + (size_t)r * ldb + k0 + c);
            }
        } else {
            // B tile: 16 rows (k) x 128 floats (n)
#pragma unroll
            for (int i = 0; i < 2; i++) {
                int s = tid + i * 256;
                int r = s >> 5, c = (s & 31) * 4;
                uint32_t dst = smB_u + (uint32_t)(buf * BS_STAGE + r * 136 + c) * 4u;
                CP_ASYNC16(dst, Bb + (size_t)(k0 + r) * ldb + c);
            }
        }
        CP_COMMIT();
    };

    float acc[4][4][4];
#pragma unroll
    for (int i = 0; i < 4; i++)
#pragma unroll
        for (int j = 0; j < 4; j++)
#pragma unroll
            for (int t = 0; t < 4; t++) acc[i][j][t] = 0.f;

    load_stage(0, 0);
    load_stage(1, 16);

    for (int c = 0; c < NC; ++c) {
        if (c + 1 < NC) CP_WAIT(1); else CP_WAIT(0);
        __syncthreads();

        const float* Ap = smA + (c & 1) * AS_STAGE;
        const float* Bp = smB + (c & 1) * BS_STAGE;
#pragma unroll
        for (int ks = 0; ks < 2; ks++) {
            uint32_t af[4][4];
#pragma unroll
            for (int i = 0; i < 4; i++) {
                int row = wm * 64 + i * 16;
                const float* base = Ap + (size_t)(row + gid) * 20 + ks * 8 + tg;
                af[i][0] = __float_as_uint(base[0]);
                af[i][1] = __float_as_uint(base[8 * 20]);
                af[i][2] = __float_as_uint(base[4]);
                af[i][3] = __float_as_uint(base[8 * 20 + 4]);
            }
            uint32_t bf[4][2];
#pragma unroll
            for (int j = 0; j < 4; j++) {
                int col = wn * 32 + j * 8;
                if (BT) {
                    const float* base = Bp + (size_t)(col + gid) * 20 + ks * 8 + tg;
                    bf[j][0] = __float_as_uint(base[0]);
                    bf[j][1] = __float_as_uint(base[4]);
                } else {
                    const float* base = Bp + (size_t)(ks * 8 + tg) * 136 + col + gid;
                    bf[j][0] = __float_as_uint(base[0]);
                    bf[j][1] = __float_as_uint(base[4 * 136]);
                }
            }
#pragma unroll
            for (int i = 0; i < 4; i++)
#pragma unroll
                for (int j = 0; j < 4; j++)
                    mma_tf32(acc[i][j], af[i][0], af[i][1], af[i][2], af[i][3],
                             bf[j][0], bf[j][1]);
        }
        __syncthreads();
        if (c + 2 < NC) load_stage(c & 1, (c + 2) * 16);
    }

    // epilogue
#pragma unroll
    for (int i = 0; i < 4; i++) {
#pragma unroll
        for (int j = 0; j < 4; j++) {
            int row = blockIdx.y * 128 + wm * 64 + i * 16 + gid;
            int col = blockIdx.x * 128 + wn * 32 + j * 8 + tg * 2;
            float* p = D + (size_t)b * sD + (size_t)row * ldd + col;
            *(float2*)p              = make_float2(acc[i][j][0], acc[i][j][1]);
            *(float2*)(p + 8 * ldd)  = make_float2(acc[i][j][2], acc[i][j][3]);
        }
    }
}

// ---------------------------------------------------------------------------
// Kernel 3: row softmax in-place, output tf32-rounded.
// Warp-shuffle reductions + one cross-warp stage (fewer barriers).
// ---------------------------------------------------------------------------
__global__ __launch_bounds__(256)
void k_softmax(float* __restrict__ S) {
    float* r = S + (size_t)blockIdx.x * SEQ;
    const int tid = threadIdx.x;
    const int lane = tid & 31;
    const int w = tid >> 5;
    __shared__ float red[8];

    float v[8];
    float m = -1e30f;
#pragma unroll
    for (int i = 0; i < 8; i++) { v[i] = r[tid + i * 256]; m = fmaxf(m, v[i]); }
#pragma unroll
    for (int o = 16; o > 0; o >>= 1) m = fmaxf(m, __shfl_xor_sync(0xffffffffu, m, o));
    if (lane == 0) red[w] = m;
    __syncthreads();
    {
        float t = red[lane & 7];
#pragma unroll
        for (int o = 4; o > 0; o >>= 1) t = fmaxf(t, __shfl_xor_sync(0xffffffffu, t, o));
        m = t;
    }

    float sum = 0.f;
#pragma unroll
    for (int i = 0; i < 8; i++) { v[i] = __expf(v[i] - m); sum += v[i]; }
#pragma unroll
    for (int o = 16; o > 0; o >>= 1) sum += __shfl_xor_sync(0xffffffffu, sum, o);
    __syncthreads();                 // red[] reuse safety
    if (lane == 0) red[w] = sum;
    __syncthreads();
    {
        float t = red[lane & 7];
#pragma unroll
        for (int o = 4; o > 0; o >>= 1) t += __shfl_xor_sync(0xffffffffu, t, o);
        sum = t;
    }
    float inv = 1.f / sum;
#pragma unroll
    for (int i = 0; i < 8; i++) r[tid + i * 256] = to_tf32(v[i] * inv);
}

// ---------------------------------------------------------------------------
extern "C" void kernel_launch(void* const* d_in, const int* in_sizes, int n_in,
                              void* d_out, int out_size) {
    const float* x = (const float*)d_in[0];
    float* out = (float*)d_out;

    float *scores, *xn, *xc;
    cudaGetSymbolAddress((void**)&scores, g_scores);
    cudaGetSymbolAddress((void**)&xn, g_xn);
    cudaGetSymbolAddress((void**)&xc, g_xc);

    // 1) normalize + tf32-round both operand copies
    k_norm<<<BATCH * SEQ, 128>>>(x, xn, xc);

    // 2) S = xn . xn^T   (NT, K = 512)
    k_mma<1, DIM><<<dim3(SEQ / 128, SEQ / 128, BATCH), 256>>>(
        xn, (size_t)SEQ * DIM, DIM,
        xn, (size_t)SEQ * DIM, DIM,
        scores, (size_t)SEQ * SEQ, SEQ);

    // 3) P = softmax(S), tf32-rounded in-place
    k_softmax<<<BATCH * SEQ, 256>>>(scores);

    // 4) O = P . X      (NN, K = 2048)
    k_mma<0, SEQ><<<dim3(DIM / 128, SEQ / 128, BATCH), 256>>>(
        scores, (size_t)SEQ * SEQ, SEQ,
        xc, (size_t)SEQ * DIM, DIM,
        out, (size_t)SEQ * DIM, DIM);
}

// round 8
// speedup vs baseline: 3.9954x; 1.2366x over previous
#include <cuda_runtime.h>
#include <cstdint>

#define BATCH 16
#define SEQ   2048
#define DIM   512

// ---------------------------------------------------------------------------
// Scratch (device globals = sanctioned no-alloc scratch)
// ---------------------------------------------------------------------------
__device__ float g_scores[(size_t)BATCH * SEQ * SEQ];   // 268 MB (S, then P tf32-rounded)
__device__ float g_xn   [(size_t)BATCH * SEQ * DIM];    // normalized x, tf32-rounded
__device__ float g_xc   [(size_t)BATCH * SEQ * DIM];    // raw x, tf32-rounded

// ---------------------------------------------------------------------------
// Helpers (baseline PTX, sm_80+ -- safe for compute_103 target)
// ---------------------------------------------------------------------------
__device__ __forceinline__ uint32_t smem_u32(const void* p) {
    uint32_t a;
    asm("{ .reg .u64 t; cvta.to.shared.u64 t, %1; cvt.u32.u64 %0, t; }" : "=r"(a) : "l"(p));
    return a;
}
__device__ __forceinline__ float to_tf32(float f) {
    uint32_t u;
    asm("cvt.rna.tf32.f32 %0, %1;" : "=r"(u) : "f"(f));
    return __uint_as_float(u);
}
#define CP_ASYNC16(dst, src) \
    asm volatile("cp.async.cg.shared.global [%0], [%1], 16;" :: "r"(dst), "l"(src))
#define CP_COMMIT() asm volatile("cp.async.commit_group;" ::: "memory")
#define CP_WAIT(n)  asm volatile("cp.async.wait_group %0;" :: "n"(n) : "memory")

__device__ __forceinline__ void mma_tf32(float* c,
                                         uint32_t a0, uint32_t a1, uint32_t a2, uint32_t a3,
                                         uint32_t b0, uint32_t b1) {
    asm volatile(
        "mma.sync.aligned.m16n8k8.row.col.f32.tf32.tf32.f32 "
        "{%0,%1,%2,%3}, {%4,%5,%6,%7}, {%8,%9}, {%0,%1,%2,%3};"
        : "+f"(c[0]), "+f"(c[1]), "+f"(c[2]), "+f"(c[3])
        : "r"(a0), "r"(a1), "r"(a2), "r"(a3), "r"(b0), "r"(b1));
}

// ---------------------------------------------------------------------------
// Kernel 1: row L2-normalize; write xn = tf32(x/|x|) and xc = tf32(x).
// ---------------------------------------------------------------------------
__global__ __launch_bounds__(128)
void k_norm(const float* __restrict__ x, float* __restrict__ xn, float* __restrict__ xc) {
    const size_t row = blockIdx.x;
    const int tid = threadIdx.x;
    float4 v = *(const float4*)(x + row * DIM + tid * 4);
    float s = v.x * v.x + v.y * v.y + v.z * v.z + v.w * v.w;
#pragma unroll
    for (int o = 16; o > 0; o >>= 1) s += __shfl_xor_sync(0xffffffffu, s, o);
    __shared__ float red[4];
    if ((tid & 31) == 0) red[tid >> 5] = s;
    __syncthreads();
    float inv = rsqrtf(red[0] + red[1] + red[2] + red[3]);
    float4 n, c;
    n.x = to_tf32(v.x * inv); n.y = to_tf32(v.y * inv);
    n.z = to_tf32(v.z * inv); n.w = to_tf32(v.w * inv);
    c.x = to_tf32(v.x); c.y = to_tf32(v.y); c.z = to_tf32(v.z); c.w = to_tf32(v.w);
    *(float4*)(xn + row * DIM + tid * 4) = n;
    *(float4*)(xc + row * DIM + tid * 4) = c;
}

// ---------------------------------------------------------------------------
// Kernel 2: tf32 mma.sync GEMM.
//   BT=1 (NT): D[m][n] = sum_k A[m][k] * B[n][k]   (both K-major)
//   BT=0 (NN): D[m][n] = sum_k A[m][k] * B[k][n]
//   SYM=1: output known symmetric; skip blocks with bx > by, write the
//          off-diagonal result to both (by,bx) and transposed (bx,by).
// Block tile 128x128, K-chunk 16, cp.async double-buffered, 256 threads,
// 8 warps (2x4), warp tile 64x32, mma m16n8k8. STATIC smem <= 48 KB.
// __launch_bounds__(256, 2): regs capped at 128 -> 2 CTAs/SM.
// ---------------------------------------------------------------------------
#define AS_STAGE 2560       // 128 rows * 20 floats (pad 16->20, conflict-free frag loads)
#define BS_STAGE_NT 2560
#define BS_STAGE_NN 2176    // 16 rows * 136 floats (pad 128->136)

template <int BT, int K, int SYM>
__global__ __launch_bounds__(256, 2)
void k_mma(const float* __restrict__ A, size_t sA, int lda,
           const float* __restrict__ B, size_t sB, int ldb,
           float* __restrict__ D, size_t sD, int ldd) {
    if (SYM && blockIdx.x > blockIdx.y) return;   // uniform early exit, no barriers yet

    constexpr int BS_STAGE = BT ? BS_STAGE_NT : BS_STAGE_NN;
    __shared__ float smA[2 * AS_STAGE];
    __shared__ float smB[2 * BS_STAGE];
    const uint32_t smA_u = smem_u32(smA);
    const uint32_t smB_u = smem_u32(smB);

    const int tid  = threadIdx.x;
    const int lane = tid & 31;
    const int wid  = tid >> 5;
    const int wm   = wid >> 2;        // 0..1
    const int wn   = wid & 3;         // 0..3
    const int gid  = lane >> 2;       // 0..7
    const int tg   = lane & 3;        // 0..3
    const int b    = blockIdx.z;

    const float* Ab = A + (size_t)b * sA + (size_t)blockIdx.y * 128 * lda;
    const float* Bb = B + (size_t)b * sB +
                      (BT ? (size_t)blockIdx.x * 128 * ldb : (size_t)blockIdx.x * 128);

    constexpr int NC = K / 16;

    auto load_stage = [&](int buf, int k0) {
        // A tile: 128 rows x 16 floats = 512 float4 segs / 256 threads
#pragma unroll
        for (int i = 0; i < 2; i++) {
            int s = tid + i * 256;
            int r = s >> 2, c = (s & 3) * 4;
            uint32_t dst = smA_u + (uint32_t)(buf * AS_STAGE + r * 20 + c) * 4u;
            CP_ASYNC16(dst, Ab + (size_t)r * lda + k0 + c);
        }
        if (BT) {
            // B tile: 128 rows (n) x 16 floats (k)
#pragma unroll
            for (int i = 0; i < 2; i++) {
                int s = tid + i * 256;
                int r = s >> 2, c = (s & 3) * 4;
                uint32_t dst = smB_u + (uint32_t)(buf * BS_STAGE + r * 20 + c) * 4u;
                CP_ASYNC16(dst, Bb + (size_t)r * ldb + k0 + c);
            }
        } else {
            // B tile: 16 rows (k) x 128 floats (n)
#pragma unroll
            for (int i = 0; i < 2; i++) {
                int s = tid + i * 256;
                int r = s >> 5, c = (s & 31) * 4;
                uint32_t dst = smB_u + (uint32_t)(buf * BS_STAGE + r * 136 + c) * 4u;
                CP_ASYNC16(dst, Bb + (size_t)(k0 + r) * ldb + c);
            }
        }
        CP_COMMIT();
    };

    float acc[4][4][4];
#pragma unroll
    for (int i = 0; i < 4; i++)
#pragma unroll
        for (int j = 0; j < 4; j++)
#pragma unroll
            for (int t = 0; t < 4; t++) acc[i][j][t] = 0.f;

    load_stage(0, 0);
    load_stage(1, 16);

    for (int c = 0; c < NC; ++c) {
        if (c + 1 < NC) CP_WAIT(1); else CP_WAIT(0);
        __syncthreads();

        const float* Ap = smA + (c & 1) * AS_STAGE;
        const float* Bp = smB + (c & 1) * BS_STAGE;
#pragma unroll
        for (int ks = 0; ks < 2; ks++) {
            uint32_t af[4][4];
#pragma unroll
            for (int i = 0; i < 4; i++) {
                int row = wm * 64 + i * 16;
                const float* base = Ap + (size_t)(row + gid) * 20 + ks * 8 + tg;
                af[i][0] = __float_as_uint(base[0]);
                af[i][1] = __float_as_uint(base[8 * 20]);
                af[i][2] = __float_as_uint(base[4]);
                af[i][3] = __float_as_uint(base[8 * 20 + 4]);
            }
            uint32_t bf[4][2];
#pragma unroll
            for (int j = 0; j < 4; j++) {
                int col = wn * 32 + j * 8;
                if (BT) {
                    const float* base = Bp + (size_t)(col + gid) * 20 + ks * 8 + tg;
                    bf[j][0] = __float_as_uint(base[0]);
                    bf[j][1] = __float_as_uint(base[4]);
                } else {
                    const float* base = Bp + (size_t)(ks * 8 + tg) * 136 + col + gid;
                    bf[j][0] = __float_as_uint(base[0]);
                    bf[j][1] = __float_as_uint(base[4 * 136]);
                }
            }
#pragma unroll
            for (int i = 0; i < 4; i++)
#pragma unroll
                for (int j = 0; j < 4; j++)
                    mma_tf32(acc[i][j], af[i][0], af[i][1], af[i][2], af[i][3],
                             bf[j][0], bf[j][1]);
        }
        __syncthreads();
        if (c + 2 < NC) load_stage(c & 1, (c + 2) * 16);
    }

    // epilogue: normal block
#pragma unroll
    for (int i = 0; i < 4; i++) {
#pragma unroll
        for (int j = 0; j < 4; j++) {
            int row = blockIdx.y * 128 + wm * 64 + i * 16 + gid;
            int col = blockIdx.x * 128 + wn * 32 + j * 8 + tg * 2;
            float* p = D + (size_t)b * sD + (size_t)row * ldd + col;
            *(float2*)p              = make_float2(acc[i][j][0], acc[i][j][1]);
            *(float2*)(p + 8 * ldd)  = make_float2(acc[i][j][2], acc[i][j][3]);
        }
    }

    // epilogue: mirrored block (transposed), off-diagonal only
    if (SYM && blockIdx.x != blockIdx.y) {
#pragma unroll
        for (int i = 0; i < 4; i++) {
#pragma unroll
            for (int j = 0; j < 4; j++) {
                int row0 = blockIdx.y * 128 + wm * 64 + i * 16 + gid;
                int col0 = blockIdx.x * 128 + wn * 32 + j * 8 + tg * 2;
                float* q = D + (size_t)b * sD;
                q[(size_t)(col0    ) * ldd + row0    ] = acc[i][j][0];
                q[(size_t)(col0 + 1) * ldd + row0    ] = acc[i][j][1];
                q[(size_t)(col0    ) * ldd + row0 + 8] = acc[i][j][2];
                q[(size_t)(col0 + 1) * ldd + row0 + 8] = acc[i][j][3];
            }
        }
    }
}

// ---------------------------------------------------------------------------
// Kernel 3: row softmax in-place, output tf32-rounded. float4 I/O,
// warp-shuffle reductions + one cross-warp stage.
// ---------------------------------------------------------------------------
__global__ __launch_bounds__(256)
void k_softmax(float* __restrict__ S) {
    float4* r = (float4*)(S + (size_t)blockIdx.x * SEQ);
    const int tid = threadIdx.x;
    const int lane = tid & 31;
    const int w = tid >> 5;
    __shared__ float red[8];

    float4 v4[2];
    v4[0] = r[tid];
    v4[1] = r[tid + 256];
    float* v = (float*)v4;

    float m = -1e30f;
#pragma unroll
    for (int i = 0; i < 8; i++) m = fmaxf(m, v[i]);
#pragma unroll
    for (int o = 16; o > 0; o >>= 1) m = fmaxf(m, __shfl_xor_sync(0xffffffffu, m, o));
    if (lane == 0) red[w] = m;
    __syncthreads();
    {
        float t = red[lane & 7];
#pragma unroll
        for (int o = 4; o > 0; o >>= 1) t = fmaxf(t, __shfl_xor_sync(0xffffffffu, t, o));
        m = t;
    }

    float sum = 0.f;
#pragma unroll
    for (int i = 0; i < 8; i++) { v[i] = __expf(v[i] - m); sum += v[i]; }
#pragma unroll
    for (int o = 16; o > 0; o >>= 1) sum += __shfl_xor_sync(0xffffffffu, sum, o);
    __syncthreads();                 // red[] reuse safety
    if (lane == 0) red[w] = sum;
    __syncthreads();
    {
        float t = red[lane & 7];
#pragma unroll
        for (int o = 4; o > 0; o >>= 1) t += __shfl_xor_sync(0xffffffffu, t, o);
        sum = t;
    }
    float inv = 1.f / sum;
#pragma unroll
    for (int i = 0; i < 8; i++) v[i] = to_tf32(v[i] * inv);
    r[tid]       = v4[0];
    r[tid + 256] = v4[1];
}

// ---------------------------------------------------------------------------
extern "C" void kernel_launch(void* const* d_in, const int* in_sizes, int n_in,
                              void* d_out, int out_size) {
    const float* x = (const float*)d_in[0];
    float* out = (float*)d_out;

    float *scores, *xn, *xc;
    cudaGetSymbolAddress((void**)&scores, g_scores);
    cudaGetSymbolAddress((void**)&xn, g_xn);
    cudaGetSymbolAddress((void**)&xc, g_xc);

    // 1) normalize + tf32-round both operand copies
    k_norm<<<BATCH * SEQ, 128>>>(x, xn, xc);

    // 2) S = xn . xn^T   (NT, K = 512, symmetric: lower-triangle blocks only)
    k_mma<1, DIM, 1><<<dim3(SEQ / 128, SEQ / 128, BATCH), 256>>>(
        xn, (size_t)SEQ * DIM, DIM,
        xn, (size_t)SEQ * DIM, DIM,
        scores, (size_t)SEQ * SEQ, SEQ);

    // 3) P = softmax(S), tf32-rounded in-place
    k_softmax<<<BATCH * SEQ, 256>>>(scores);

    // 4) O = P . X      (NN, K = 2048)
    k_mma<0, SEQ, 0><<<dim3(DIM / 128, SEQ / 128, BATCH), 256>>>(
        scores, (size_t)SEQ * SEQ, SEQ,
        xc, (size_t)SEQ * DIM, DIM,
        out, (size_t)SEQ * DIM, DIM);
}

// round 9
// speedup vs baseline: 4.1117x; 1.0291x over previous
#include <cuda_runtime.h>
#include <cstdint>

#define BATCH 16
#define SEQ   2048
#define DIM   512

// ---------------------------------------------------------------------------
// Scratch (device globals = sanctioned no-alloc scratch)
// ---------------------------------------------------------------------------
__device__ float g_scores[(size_t)BATCH * SEQ * SEQ];   // 268 MB (S, then P tf32-rounded)
__device__ float g_xn   [(size_t)BATCH * SEQ * DIM];    // normalized x, tf32-rounded
__device__ float g_xc   [(size_t)BATCH * SEQ * DIM];    // raw x, tf32-rounded

// ---------------------------------------------------------------------------
// Helpers (baseline PTX, sm_75+/sm_80+ -- safe for compute_103 target)
// ---------------------------------------------------------------------------
__device__ __forceinline__ uint32_t smem_u32(const void* p) {
    uint32_t a;
    asm("{ .reg .u64 t; cvta.to.shared.u64 t, %1; cvt.u32.u64 %0, t; }" : "=r"(a) : "l"(p));
    return a;
}
__device__ __forceinline__ float to_tf32(float f) {
    uint32_t u;
    asm("cvt.rna.tf32.f32 %0, %1;" : "=r"(u) : "f"(f));
    return __uint_as_float(u);
}
#define CP_ASYNC16(dst, src) \
    asm volatile("cp.async.cg.shared.global [%0], [%1], 16;" :: "r"(dst), "l"(src))
#define CP_COMMIT() asm volatile("cp.async.commit_group;" ::: "memory")
#define CP_WAIT(n)  asm volatile("cp.async.wait_group %0;" :: "n"(n) : "memory")

__device__ __forceinline__ void ldsm_x4(uint32_t& r0, uint32_t& r1, uint32_t& r2, uint32_t& r3,
                                        uint32_t addr) {
    asm volatile("ldmatrix.sync.aligned.m8n8.x4.shared.b16 {%0,%1,%2,%3}, [%4];"
                 : "=r"(r0), "=r"(r1), "=r"(r2), "=r"(r3) : "r"(addr));
}

__device__ __forceinline__ void mma_tf32(float* c,
                                         uint32_t a0, uint32_t a1, uint32_t a2, uint32_t a3,
                                         uint32_t b0, uint32_t b1) {
    asm volatile(
        "mma.sync.aligned.m16n8k8.row.col.f32.tf32.tf32.f32 "
        "{%0,%1,%2,%3}, {%4,%5,%6,%7}, {%8,%9}, {%0,%1,%2,%3};"
        : "+f"(c[0]), "+f"(c[1]), "+f"(c[2]), "+f"(c[3])
        : "r"(a0), "r"(a1), "r"(a2), "r"(a3), "r"(b0), "r"(b1));
}

// ---------------------------------------------------------------------------
// Kernel 1: row L2-normalize; write xn = tf32(x/|x|) and xc = tf32(x).
// ---------------------------------------------------------------------------
__global__ __launch_bounds__(128)
void k_norm(const float* __restrict__ x, float* __restrict__ xn, float* __restrict__ xc) {
    const size_t row = blockIdx.x;
    const int tid = threadIdx.x;
    float4 v = *(const float4*)(x + row * DIM + tid * 4);
    float s = v.x * v.x + v.y * v.y + v.z * v.z + v.w * v.w;
#pragma unroll
    for (int o = 16; o > 0; o >>= 1) s += __shfl_xor_sync(0xffffffffu, s, o);
    __shared__ float red[4];
    if ((tid & 31) == 0) red[tid >> 5] = s;
    __syncthreads();
    float inv = rsqrtf(red[0] + red[1] + red[2] + red[3]);
    float4 n, c;
    n.x = to_tf32(v.x * inv); n.y = to_tf32(v.y * inv);
    n.z = to_tf32(v.z * inv); n.w = to_tf32(v.w * inv);
    c.x = to_tf32(v.x); c.y = to_tf32(v.y); c.z = to_tf32(v.z); c.w = to_tf32(v.w);
    *(float4*)(xn + row * DIM + tid * 4) = n;
    *(float4*)(xc + row * DIM + tid * 4) = c;
}

// ---------------------------------------------------------------------------
// Kernel 2: tf32 mma.sync GEMM with ldmatrix fragment loads.
//   BT=1 (NT): D[m][n] = sum_k A[m][k] * B[n][k]   (both K-major)
//   BT=0 (NN): D[m][n] = sum_k A[m][k] * B[k][n]
//   SYM=1: output symmetric; skip bx > by, write mirrored block transposed.
// Block tile 128x128, K-chunk 16, cp.async double-buffered, 256 threads,
// 8 warps (2x4), warp tile 64x32, mma m16n8k8. STATIC smem <= 48 KB.
// __launch_bounds__(256, 2): regs capped at 128 -> 2 CTAs/SM.
// ---------------------------------------------------------------------------
#define AS_STAGE 2560       // 128 rows * 20 floats (pad 16->20; LDSM conflict-free)
#define BS_STAGE_NT 2560
#define BS_STAGE_NN 2176    // 16 rows * 136 floats (pad 128->136)

template <int BT, int K, int SYM>
__global__ __launch_bounds__(256, 2)
void k_mma(const float* __restrict__ A, size_t sA, int lda,
           const float* __restrict__ B, size_t sB, int ldb,
           float* __restrict__ D, size_t sD, int ldd) {
    if (SYM && blockIdx.x > blockIdx.y) return;   // uniform early exit, before barriers

    constexpr int BS_STAGE = BT ? BS_STAGE_NT : BS_STAGE_NN;
    __shared__ float smA[2 * AS_STAGE];
    __shared__ float smB[2 * BS_STAGE];
    const uint32_t smA_u = smem_u32(smA);
    const uint32_t smB_u = smem_u32(smB);

    const int tid  = threadIdx.x;
    const int lane = tid & 31;
    const int wid  = tid >> 5;
    const int wm   = wid >> 2;        // 0..1
    const int wn   = wid & 3;         // 0..3
    const int gid  = lane >> 2;       // 0..7
    const int tg   = lane & 3;        // 0..3
    const int b    = blockIdx.z;

    const float* Ab = A + (size_t)b * sA + (size_t)blockIdx.y * 128 * lda;
    const float* Bb = B + (size_t)b * sB +
                      (BT ? (size_t)blockIdx.x * 128 * ldb : (size_t)blockIdx.x * 128);

    constexpr int NC = K / 16;

    auto load_stage = [&](int buf, int k0) {
        // A tile: 128 rows x 16 floats = 512 float4 segs / 256 threads
#pragma unroll
        for (int i = 0; i < 2; i++) {
            int s = tid + i * 256;
            int r = s >> 2, c = (s & 3) * 4;
            uint32_t dst = smA_u + (uint32_t)(buf * AS_STAGE + r * 20 + c) * 4u;
            CP_ASYNC16(dst, Ab + (size_t)r * lda + k0 + c);
        }
        if (BT) {
#pragma unroll
            for (int i = 0; i < 2; i++) {
                int s = tid + i * 256;
                int r = s >> 2, c = (s & 3) * 4;
                uint32_t dst = smB_u + (uint32_t)(buf * BS_STAGE + r * 20 + c) * 4u;
                CP_ASYNC16(dst, Bb + (size_t)r * ldb + k0 + c);
            }
        } else {
#pragma unroll
            for (int i = 0; i < 2; i++) {
                int s = tid + i * 256;
                int r = s >> 5, c = (s & 31) * 4;
                uint32_t dst = smB_u + (uint32_t)(buf * BS_STAGE + r * 136 + c) * 4u;
                CP_ASYNC16(dst, Bb + (size_t)(k0 + r) * ldb + c);
            }
        }
        CP_COMMIT();
    };

    float acc[4][4][4];
#pragma unroll
    for (int i = 0; i < 4; i++)
#pragma unroll
        for (int j = 0; j < 4; j++)
#pragma unroll
            for (int t = 0; t < 4; t++) acc[i][j][t] = 0.f;

    // ldmatrix per-lane address components (byte offsets within a stage)
    // A x4 (one 16x8 b32 tile): lanes 0-15 rows, lanes 16-31 same rows, k+4
    const uint32_t aLdsmOff = (uint32_t)((lane & 15) * 20 + (lane >> 4) * 4) * 4u;
    // B-NT x4 (8 n-rows, k 0..15 in 4-col quads): quad = lane>>3
    const uint32_t bLdsmOff = (uint32_t)((lane & 7) * 20 + (lane >> 3) * 4) * 4u;

    load_stage(0, 0);
    load_stage(1, 16);

    for (int c = 0; c < NC; ++c) {
        if (c + 1 < NC) CP_WAIT(1); else CP_WAIT(0);
        __syncthreads();

        const uint32_t ApU = smA_u + (uint32_t)((c & 1) * AS_STAGE) * 4u;
        const uint32_t BpU = smB_u + (uint32_t)((c & 1) * BS_STAGE) * 4u;
        const float*  Bp  = smB + (c & 1) * BS_STAGE;

        // --- B fragments for the whole chunk ---
        uint32_t bfr[4][4];   // [j][ks*2 + {b0,b1}]
        if (BT) {
#pragma unroll
            for (int j = 0; j < 4; j++) {
                uint32_t addr = BpU + (uint32_t)((wn * 32 + j * 8) * 20) * 4u + bLdsmOff;
                ldsm_x4(bfr[j][0], bfr[j][1], bfr[j][2], bfr[j][3], addr);
            }
        } else {
#pragma unroll
            for (int ks = 0; ks < 2; ks++)
#pragma unroll
                for (int j = 0; j < 4; j++) {
                    const float* base = Bp + (size_t)(ks * 8 + tg) * 136 + wn * 32 + j * 8 + gid;
                    bfr[j][ks * 2 + 0] = __float_as_uint(base[0]);
                    bfr[j][ks * 2 + 1] = __float_as_uint(base[4 * 136]);
                }
        }

#pragma unroll
        for (int ks = 0; ks < 2; ks++) {
            uint32_t af[4][4];
#pragma unroll
            for (int i = 0; i < 4; i++) {
                uint32_t addr = ApU + (uint32_t)((wm * 64 + i * 16) * 20 + ks * 8) * 4u + aLdsmOff;
                ldsm_x4(af[i][0], af[i][1], af[i][2], af[i][3], addr);
            }
#pragma unroll
            for (int i = 0; i < 4; i++)
#pragma unroll
                for (int j = 0; j < 4; j++)
                    mma_tf32(acc[i][j], af[i][0], af[i][1], af[i][2], af[i][3],
                             bfr[j][ks * 2 + 0], bfr[j][ks * 2 + 1]);
        }
        __syncthreads();
        if (c + 2 < NC) load_stage(c & 1, (c + 2) * 16);
    }

    // epilogue: normal block
#pragma unroll
    for (int i = 0; i < 4; i++) {
#pragma unroll
        for (int j = 0; j < 4; j++) {
            int row = blockIdx.y * 128 + wm * 64 + i * 16 + gid;
            int col = blockIdx.x * 128 + wn * 32 + j * 8 + tg * 2;
            float* p = D + (size_t)b * sD + (size_t)row * ldd + col;
            *(float2*)p              = make_float2(acc[i][j][0], acc[i][j][1]);
            *(float2*)(p + 8 * ldd)  = make_float2(acc[i][j][2], acc[i][j][3]);
        }
    }

    // epilogue: mirrored block (transposed), off-diagonal only
    if (SYM && blockIdx.x != blockIdx.y) {
#pragma unroll
        for (int i = 0; i < 4; i++) {
#pragma unroll
            for (int j = 0; j < 4; j++) {
                int row0 = blockIdx.y * 128 + wm * 64 + i * 16 + gid;
                int col0 = blockIdx.x * 128 + wn * 32 + j * 8 + tg * 2;
                float* q = D + (size_t)b * sD;
                q[(size_t)(col0    ) * ldd + row0    ] = acc[i][j][0];
                q[(size_t)(col0 + 1) * ldd + row0    ] = acc[i][j][1];
                q[(size_t)(col0    ) * ldd + row0 + 8] = acc[i][j][2];
                q[(size_t)(col0 + 1) * ldd + row0 + 8] = acc[i][j][3];
            }
        }
    }
}

// ---------------------------------------------------------------------------
// Kernel 3: row softmax in-place, output tf32-rounded. float4 I/O,
// warp-shuffle reductions + one cross-warp stage.
// ---------------------------------------------------------------------------
__global__ __launch_bounds__(256)
void k_softmax(float* __restrict__ S) {
    float4* r = (float4*)(S + (size_t)blockIdx.x * SEQ);
    const int tid = threadIdx.x;
    const int lane = tid & 31;
    const int w = tid >> 5;
    __shared__ float red[8];

    float4 v4[2];
    v4[0] = r[tid];
    v4[1] = r[tid + 256];
    float* v = (float*)v4;

    float m = -1e30f;
#pragma unroll
    for (int i = 0; i < 8; i++) m = fmaxf(m, v[i]);
#pragma unroll
    for (int o = 16; o > 0; o >>= 1) m = fmaxf(m, __shfl_xor_sync(0xffffffffu, m, o));
    if (lane == 0) red[w] = m;
    __syncthreads();
    {
        float t = red[lane & 7];
#pragma unroll
        for (int o = 4; o > 0; o >>= 1) t = fmaxf(t, __shfl_xor_sync(0xffffffffu, t, o));
        m = t;
    }

    float sum = 0.f;
#pragma unroll
    for (int i = 0; i < 8; i++) { v[i] = __expf(v[i] - m); sum += v[i]; }
#pragma unroll
    for (int o = 16; o > 0; o >>= 1) sum += __shfl_xor_sync(0xffffffffu, sum, o);
    __syncthreads();                 // red[] reuse safety
    if (lane == 0) red[w] = sum;
    __syncthreads();
    {
        float t = red[lane & 7];
#pragma unroll
        for (int o = 4; o > 0; o >>= 1) t += __shfl_xor_sync(0xffffffffu, t, o);
        sum = t;
    }
    float inv = 1.f / sum;
#pragma unroll
    for (int i = 0; i < 8; i++) v[i] = to_tf32(v[i] * inv);
    r[tid]       = v4[0];
    r[tid + 256] = v4[1];
}

// ---------------------------------------------------------------------------
extern "C" void kernel_launch(void* const* d_in, const int* in_sizes, int n_in,
                              void* d_out, int out_size) {
    const float* x = (const float*)d_in[0];
    float* out = (float*)d_out;

    float *scores, *xn, *xc;
    cudaGetSymbolAddress((void**)&scores, g_scores);
    cudaGetSymbolAddress((void**)&xn, g_xn);
    cudaGetSymbolAddress((void**)&xc, g_xc);

    // 1) normalize + tf32-round both operand copies
    k_norm<<<BATCH * SEQ, 128>>>(x, xn, xc);

    // 2) S = xn . xn^T   (NT, K = 512, symmetric: lower-triangle blocks only)
    k_mma<1, DIM, 1><<<dim3(SEQ / 128, SEQ / 128, BATCH), 256>>>(
        xn, (size_t)SEQ * DIM, DIM,
        xn, (size_t)SEQ * DIM, DIM,
        scores, (size_t)SEQ * SEQ, SEQ);

    // 3) P = softmax(S), tf32-rounded in-place
    k_softmax<<<BATCH * SEQ, 256>>>(scores);

    // 4) O = P . X      (NN, K = 2048)
    k_mma<0, SEQ, 0><<<dim3(DIM / 128, SEQ / 128, BATCH), 256>>>(
        scores, (size_t)SEQ * SEQ, SEQ,
        xc, (size_t)SEQ * DIM, DIM,
        out, (size_t)SEQ * DIM, DIM);
}

// round 12
// speedup vs baseline: 4.2975x; 1.0452x over previous
#include <cuda_runtime.h>
#include <cstdint>

#define BATCH 16
#define SEQ   2048
#define DIM   512

// ---------------------------------------------------------------------------
// Scratch (device globals = sanctioned no-alloc scratch)
// ---------------------------------------------------------------------------
__device__ float g_scores[(size_t)BATCH * SEQ * SEQ];   // 268 MB (S, then P tf32-rounded)
__device__ float g_xn   [(size_t)BATCH * SEQ * DIM];    // normalized x, tf32-rounded
__device__ float g_xc   [(size_t)BATCH * SEQ * DIM];    // raw x, tf32-rounded

// ---------------------------------------------------------------------------
// Helpers (baseline PTX, sm_75+/sm_80+ -- safe for compute_103 target)
// ---------------------------------------------------------------------------
__device__ __forceinline__ uint32_t smem_u32(const void* p) {
    uint32_t a;
    asm("{ .reg .u64 t; cvta.to.shared.u64 t, %1; cvt.u32.u64 %0, t; }" : "=r"(a) : "l"(p));
    return a;
}
__device__ __forceinline__ float to_tf32(float f) {
    uint32_t u;
    asm("cvt.rna.tf32.f32 %0, %1;" : "=r"(u) : "f"(f));
    return __uint_as_float(u);
}
#define CP_ASYNC16(dst, src) \
    asm volatile("cp.async.cg.shared.global [%0], [%1], 16;" :: "r"(dst), "l"(src))
#define CP_COMMIT() asm volatile("cp.async.commit_group;" ::: "memory")
#define CP_WAIT(n)  asm volatile("cp.async.wait_group %0;" :: "n"(n) : "memory")

__device__ __forceinline__ void ldsm_x4(uint32_t& r0, uint32_t& r1, uint32_t& r2, uint32_t& r3,
                                        uint32_t addr) {
    asm volatile("ldmatrix.sync.aligned.m8n8.x4.shared.b16 {%0,%1,%2,%3}, [%4];"
                 : "=r"(r0), "=r"(r1), "=r"(r2), "=r"(r3) : "r"(addr));
}

__device__ __forceinline__ void mma_tf32(float* c,
                                         uint32_t a0, uint32_t a1, uint32_t a2, uint32_t a3,
                                         uint32_t b0, uint32_t b1) {
    asm volatile(
        "mma.sync.aligned.m16n8k8.row.col.f32.tf32.tf32.f32 "
        "{%0,%1,%2,%3}, {%4,%5,%6,%7}, {%8,%9}, {%0,%1,%2,%3};"
        : "+f"(c[0]), "+f"(c[1]), "+f"(c[2]), "+f"(c[3])
        : "r"(a0), "r"(a1), "r"(a2), "r"(a3), "r"(b0), "r"(b1));
}

// ---------------------------------------------------------------------------
// Kernel 1: row L2-normalize; write xn = tf32(x/|x|) and xc = tf32(x).
// ---------------------------------------------------------------------------
__global__ __launch_bounds__(128)
void k_norm(const float* __restrict__ x, float* __restrict__ xn, float* __restrict__ xc) {
    const size_t row = blockIdx.x;
    const int tid = threadIdx.x;
    float4 v = *(const float4*)(x + row * DIM + tid * 4);
    float s = v.x * v.x + v.y * v.y + v.z * v.z + v.w * v.w;
#pragma unroll
    for (int o = 16; o > 0; o >>= 1) s += __shfl_xor_sync(0xffffffffu, s, o);
    __shared__ float red[4];
    if ((tid & 31) == 0) red[tid >> 5] = s;
    __syncthreads();
    float inv = rsqrtf(red[0] + red[1] + red[2] + red[3]);
    float4 n, c;
    n.x = to_tf32(v.x * inv); n.y = to_tf32(v.y * inv);
    n.z = to_tf32(v.z * inv); n.w = to_tf32(v.w * inv);
    c.x = to_tf32(v.x); c.y = to_tf32(v.y); c.z = to_tf32(v.z); c.w = to_tf32(v.w);
    *(float4*)(xn + row * DIM + tid * 4) = n;
    *(float4*)(xc + row * DIM + tid * 4) = c;
}

// ---------------------------------------------------------------------------
// Kernel 2: tf32 mma.sync GEMM, K-chunk 32.
//   BT=1 (NT): D[m][n] = sum_k A[m][k] * B[n][k]   (both K-major)
//   BT=0 (NN): D[m][n] = sum_k A[m][k] * B[k][n]
//   SYM=1: output symmetric; skip bx > by, write mirrored block transposed.
// A: 2-stage cp.async, 128x32 fp32 per stage, 128B rows, XOR-16B-chunk swizzle.
// B: 1 stage, register-staged (LDG at iter c-1, smem store at iter c).
// 2 barriers per K=32 chunk. STATIC smem = 48 KB exactly.
// __launch_bounds__(256, 2): regs capped at 128 -> 2 CTAs/SM.
// ---------------------------------------------------------------------------
template <int BT, int K, int SYM>
__global__ __launch_bounds__(256, 2)
void k_mma(const float* __restrict__ A, size_t sA, int lda,
           const float* __restrict__ B, size_t sB, int ldb,
           float* __restrict__ D, size_t sD, int ldd) {
    if (SYM && blockIdx.x > blockIdx.y) return;   // uniform early exit, before barriers

    __shared__ __align__(128) float smA[8192];    // 2 stages x 128x32 = 32 KB
    __shared__ __align__(128) float smB[4096];    // 1 stage 16 KB (NT:128x32, NN:32x128)
    const uint32_t smA_u = smem_u32(smA);
    const uint32_t smB_u = smem_u32(smB);

    const int tid  = threadIdx.x;
    const int lane = tid & 31;
    const int wid  = tid >> 5;
    const int wm   = wid >> 2;        // 0..1
    const int wn   = wid & 3;         // 0..3
    const int gid  = lane >> 2;       // 0..7
    const int tg   = lane & 3;        // 0..3
    const int b    = blockIdx.z;

    const float* Ab = A + (size_t)b * sA + (size_t)blockIdx.y * 128 * lda;
    const float* Bb = B + (size_t)b * sB +
                      (BT ? (size_t)blockIdx.x * 128 * ldb : (size_t)blockIdx.x * 128);

    constexpr int NC = K / 32;

    // ---- A: cp.async into XOR-swizzled stage ----
    auto load_A = [&](int stg, int c) {
        const int k0 = c * 32;
#pragma unroll
        for (int i = 0; i < 4; i++) {
            int s  = tid + i * 256;          // 0..1023 : 16B chunk id
            int r  = s >> 3;                 // row 0..127
            int ck = s & 7;                  // 16B chunk within row
            int ph = ck ^ (r & 7);
            uint32_t dst = smA_u + (uint32_t)(stg * 16384 + r * 128 + ph * 16);
            CP_ASYNC16(dst, Ab + (size_t)r * lda + k0 + ck * 4);
        }
        CP_COMMIT();
    };

    // ---- B: register staging ----
    float4 breg[4];
    auto ldg_B = [&](int c) {
        const int k0 = c * 32;
        if (BT) {
#pragma unroll
            for (int i = 0; i < 4; i++) {
                int s = tid + i * 256, r = s >> 3, ck = s & 7;
                breg[i] = *(const float4*)(Bb + (size_t)r * ldb + k0 + ck * 4);
            }
        } else {
#pragma unroll
            for (int i = 0; i < 4; i++) {
                int s = tid + i * 256, r = s >> 5, ck = s & 31;
                breg[i] = *(const float4*)(Bb + (size_t)(k0 + r) * ldb + ck * 4);
            }
        }
    };
    auto store_B = [&]() {
        if (BT) {
#pragma unroll
            for (int i = 0; i < 4; i++) {
                int s = tid + i * 256, r = s >> 3, ck = s & 7;
                int ph = ck ^ (r & 7);
                *(float4*)((char*)smB + r * 128 + ph * 16) = breg[i];
            }
        } else {
#pragma unroll
            for (int i = 0; i < 4; i++) {
                int s = tid + i * 256, r = s >> 5, ck = s & 31;
                int ph = (ck & ~7) | ((ck + 2 * (r & 3)) & 7);   // rotate within 128B group
                *(float4*)((char*)smB + r * 512 + ph * 16) = breg[i];
            }
        }
    };

    float acc[4][4][4];
#pragma unroll
    for (int i = 0; i < 4; i++)
#pragma unroll
        for (int j = 0; j < 4; j++)
#pragma unroll
            for (int t = 0; t < 4; t++) acc[i][j][t] = 0.f;

    const int aRowL = lane & 15;      // A ldsm: local row within 16-row tile
    const int aQ    = lane >> 4;      // A ldsm: 16B chunk select (0/1)

    load_A(0, 0);
    ldg_B(0);

    for (int c = 0; c < NC; ++c) {
        __syncthreads();                      // compute(c-1) done: A stage (c+1)&1 + B smem free
        if (c + 1 < NC) load_A((c + 1) & 1, c + 1);
        store_B();
        if (c + 1 < NC) ldg_B(c + 1);
        if (c + 1 < NC) CP_WAIT(1); else CP_WAIT(0);   // A(c) complete
        __syncthreads();                      // A(c) + B(c) visible

        const uint32_t ApU = smA_u + (uint32_t)((c & 1) * 16384);

        if (BT) {
#pragma unroll
            for (int p = 0; p < 2; p++) {
                uint32_t bq[4][4];
#pragma unroll
                for (int j = 0; j < 4; j++) {
                    int r  = wn * 32 + j * 8 + (lane & 7);
                    int ck = p * 4 + (lane >> 3);
                    int ph = ck ^ (r & 7);
                    ldsm_x4(bq[j][0], bq[j][1], bq[j][2], bq[j][3],
                            smB_u + (uint32_t)(r * 128 + ph * 16));
                }
#pragma unroll
                for (int s2 = 0; s2 < 2; s2++) {
                    const int ks = p * 2 + s2;
                    uint32_t af[4][4];
#pragma unroll
                    for (int i = 0; i < 4; i++) {
                        int r  = wm * 64 + i * 16 + aRowL;
                        int ck = ks * 2 + aQ;
                        int ph = ck ^ (r & 7);
                        ldsm_x4(af[i][0], af[i][1], af[i][2], af[i][3],
                                ApU + (uint32_t)(r * 128 + ph * 16));
                    }
#pragma unroll
                    for (int i = 0; i < 4; i++)
#pragma unroll
                        for (int j = 0; j < 4; j++)
                            mma_tf32(acc[i][j], af[i][0], af[i][1], af[i][2], af[i][3],
                                     bq[j][s2 * 2 + 0], bq[j][s2 * 2 + 1]);
                }
            }
        } else {
#pragma unroll
            for (int ks = 0; ks < 4; ks++) {
                uint32_t af[4][4];
#pragma unroll
                for (int i = 0; i < 4; i++) {
                    int r  = wm * 64 + i * 16 + aRowL;
                    int ck = ks * 2 + aQ;
                    int ph = ck ^ (r & 7);
                    ldsm_x4(af[i][0], af[i][1], af[i][2], af[i][3],
                            ApU + (uint32_t)(r * 128 + ph * 16));
                }
                uint32_t bf[4][2];
#pragma unroll
                for (int j = 0; j < 4; j++) {
                    int col = wn * 32 + j * 8 + gid;
                    int kk  = ks * 8 + tg;
                    int ck  = col >> 2;
                    int ph  = (ck & ~7) | ((ck + 2 * (kk & 3)) & 7);
                    const char* base = (const char*)smB + ph * 16 + (col & 3) * 4;
                    bf[j][0] = *(const uint32_t*)(base + kk * 512);
                    bf[j][1] = *(const uint32_t*)(base + (kk + 4) * 512);   // same rotation: (kk+4)&3 == kk&3
                }
#pragma unroll
                for (int i = 0; i < 4; i++)
#pragma unroll
                    for (int j = 0; j < 4; j++)
                        mma_tf32(acc[i][j], af[i][0], af[i][1], af[i][2], af[i][3],
                                 bf[j][0], bf[j][1]);
            }
        }
    }

    // epilogue: normal block
#pragma unroll
    for (int i = 0; i < 4; i++) {
#pragma unroll
        for (int j = 0; j < 4; j++) {
            int row = blockIdx.y * 128 + wm * 64 + i * 16 + gid;
            int col = blockIdx.x * 128 + wn * 32 + j * 8 + tg * 2;
            float* p = D + (size_t)b * sD + (size_t)row * ldd + col;
            *(float2*)p              = make_float2(acc[i][j][0], acc[i][j][1]);
            *(float2*)(p + 8 * ldd)  = make_float2(acc[i][j][2], acc[i][j][3]);
        }
    }

    // epilogue: mirrored block (transposed), off-diagonal only
    if (SYM && blockIdx.x != blockIdx.y) {
#pragma unroll
        for (int i = 0; i < 4; i++) {
#pragma unroll
            for (int j = 0; j < 4; j++) {
                int row0 = blockIdx.y * 128 + wm * 64 + i * 16 + gid;
                int col0 = blockIdx.x * 128 + wn * 32 + j * 8 + tg * 2;
                float* q = D + (size_t)b * sD;
                q[(size_t)(col0    ) * ldd + row0    ] = acc[i][j][0];
                q[(size_t)(col0 + 1) * ldd + row0    ] = acc[i][j][1];
                q[(size_t)(col0    ) * ldd + row0 + 8] = acc[i][j][2];
                q[(size_t)(col0 + 1) * ldd + row0 + 8] = acc[i][j][3];
            }
        }
    }
}

// ---------------------------------------------------------------------------
// Kernel 3: row softmax in-place, output tf32-rounded. float4 I/O,
// warp-shuffle reductions + one cross-warp stage.
// ---------------------------------------------------------------------------
__global__ __launch_bounds__(256)
void k_softmax(float* __restrict__ S) {
    float4* r = (float4*)(S + (size_t)blockIdx.x * SEQ);
    const int tid = threadIdx.x;
    const int lane = tid & 31;
    const int w = tid >> 5;
    __shared__ float red[8];

    float4 v4[2];
    v4[0] = r[tid];
    v4[1] = r[tid + 256];
    float* v = (float*)v4;

    float m = -1e30f;
#pragma unroll
    for (int i = 0; i < 8; i++) m = fmaxf(m, v[i]);
#pragma unroll
    for (int o = 16; o > 0; o >>= 1) m = fmaxf(m, __shfl_xor_sync(0xffffffffu, m, o));
    if (lane == 0) red[w] = m;
    __syncthreads();
    {
        float t = red[lane & 7];
#pragma unroll
        for (int o = 4; o > 0; o >>= 1) t = fmaxf(t, __shfl_xor_sync(0xffffffffu, t, o));
        m = t;
    }

    float sum = 0.f;
#pragma unroll
    for (int i = 0; i < 8; i++) { v[i] = __expf(v[i] - m); sum += v[i]; }
#pragma unroll
    for (int o = 16; o > 0; o >>= 1) sum += __shfl_xor_sync(0xffffffffu, sum, o);
    __syncthreads();                 // red[] reuse safety
    if (lane == 0) red[w] = sum;
    __syncthreads();
    {
        float t = red[lane & 7];
#pragma unroll
        for (int o = 4; o > 0; o >>= 1) t += __shfl_xor_sync(0xffffffffu, t, o);
        sum = t;
    }
    float inv = 1.f / sum;
#pragma unroll
    for (int i = 0; i < 8; i++) v[i] = to_tf32(v[i] * inv);
    r[tid]       = v4[0];
    r[tid + 256] = v4[1];
}

// ---------------------------------------------------------------------------
extern "C" void kernel_launch(void* const* d_in, const int* in_sizes, int n_in,
                              void* d_out, int out_size) {
    const float* x = (const float*)d_in[0];
    float* out = (float*)d_out;

    float *scores, *xn, *xc;
    cudaGetSymbolAddress((void**)&scores, g_scores);
    cudaGetSymbolAddress((void**)&xn, g_xn);
    cudaGetSymbolAddress((void**)&xc, g_xc);

    // 1) normalize + tf32-round both operand copies
    k_norm<<<BATCH * SEQ, 128>>>(x, xn, xc);

    // 2) S = xn . xn^T   (NT, K = 512, symmetric: lower-triangle blocks only)
    k_mma<1, DIM, 1><<<dim3(SEQ / 128, SEQ / 128, BATCH), 256>>>(
        xn, (size_t)SEQ * DIM, DIM,
        xn, (size_t)SEQ * DIM, DIM,
        scores, (size_t)SEQ * SEQ, SEQ);

    // 3) P = softmax(S), tf32-rounded in-place
    k_softmax<<<BATCH * SEQ, 256>>>(scores);

    // 4) O = P . X      (NN, K = 2048)
    k_mma<0, SEQ, 0><<<dim3(DIM / 128, SEQ / 128, BATCH), 256>>>(
        scores, (size_t)SEQ * SEQ, SEQ,
        xc, (size_t)SEQ * DIM, DIM,
        out, (size_t)SEQ * DIM, DIM);
}

// round 13
// speedup vs baseline: 4.7034x; 1.0944x over previous
#include <cuda_runtime.h>
#include <cstdint>

#define BATCH 16
#define SEQ   2048
#define DIM   512

// ---------------------------------------------------------------------------
// Scratch (device globals = sanctioned no-alloc scratch)
// ---------------------------------------------------------------------------
__device__ float g_scores[(size_t)BATCH * SEQ * SEQ];   // 268 MB raw scores S
__device__ float g_xn   [(size_t)BATCH * SEQ * DIM];    // normalized x, tf32-rounded
__device__ float g_xc   [(size_t)BATCH * SEQ * DIM];    // raw x, tf32-rounded

// ---------------------------------------------------------------------------
// Helpers (baseline PTX, sm_75+/sm_80+ -- safe for compute_103 target)
// ---------------------------------------------------------------------------
__device__ __forceinline__ uint32_t smem_u32(const void* p) {
    uint32_t a;
    asm("{ .reg .u64 t; cvta.to.shared.u64 t, %1; cvt.u32.u64 %0, t; }" : "=r"(a) : "l"(p));
    return a;
}
__device__ __forceinline__ float to_tf32(float f) {
    uint32_t u;
    asm("cvt.rna.tf32.f32 %0, %1;" : "=r"(u) : "f"(f));
    return __uint_as_float(u);
}
#define CP_ASYNC16(dst, src) \
    asm volatile("cp.async.cg.shared.global [%0], [%1], 16;" :: "r"(dst), "l"(src))
#define CP_COMMIT() asm volatile("cp.async.commit_group;" ::: "memory")
#define CP_WAIT(n)  asm volatile("cp.async.wait_group %0;" :: "n"(n) : "memory")

__device__ __forceinline__ void ldsm_x4(uint32_t& r0, uint32_t& r1, uint32_t& r2, uint32_t& r3,
                                        uint32_t addr) {
    asm volatile("ldmatrix.sync.aligned.m8n8.x4.shared.b16 {%0,%1,%2,%3}, [%4];"
                 : "=r"(r0), "=r"(r1), "=r"(r2), "=r"(r3) : "r"(addr));
}

__device__ __forceinline__ void mma_tf32(float* c,
                                         uint32_t a0, uint32_t a1, uint32_t a2, uint32_t a3,
                                         uint32_t b0, uint32_t b1) {
    asm volatile(
        "mma.sync.aligned.m16n8k8.row.col.f32.tf32.tf32.f32 "
        "{%0,%1,%2,%3}, {%4,%5,%6,%7}, {%8,%9}, {%0,%1,%2,%3};"
        : "+f"(c[0]), "+f"(c[1]), "+f"(c[2]), "+f"(c[3])
        : "r"(a0), "r"(a1), "r"(a2), "r"(a3), "r"(b0), "r"(b1));
}

// ---------------------------------------------------------------------------
// Kernel 1: row L2-normalize; write xn = tf32(x/|x|) and xc = tf32(x).
// ---------------------------------------------------------------------------
__global__ __launch_bounds__(128)
void k_norm(const float* __restrict__ x, float* __restrict__ xn, float* __restrict__ xc) {
    const size_t row = blockIdx.x;
    const int tid = threadIdx.x;
    float4 v = *(const float4*)(x + row * DIM + tid * 4);
    float s = v.x * v.x + v.y * v.y + v.z * v.z + v.w * v.w;
#pragma unroll
    for (int o = 16; o > 0; o >>= 1) s += __shfl_xor_sync(0xffffffffu, s, o);
    __shared__ float red[4];
    if ((tid & 31) == 0) red[tid >> 5] = s;
    __syncthreads();
    float inv = rsqrtf(red[0] + red[1] + red[2] + red[3]);
    float4 n, c;
    n.x = to_tf32(v.x * inv); n.y = to_tf32(v.y * inv);
    n.z = to_tf32(v.z * inv); n.w = to_tf32(v.w * inv);
    c.x = to_tf32(v.x); c.y = to_tf32(v.y); c.z = to_tf32(v.z); c.w = to_tf32(v.w);
    *(float4*)(xn + row * DIM + tid * 4) = n;
    *(float4*)(xc + row * DIM + tid * 4) = c;
}

// ---------------------------------------------------------------------------
// Kernel 2: GEMM1 = NT tf32 mma.sync, S = xn . xn^T, symmetric (lower blocks).
// A: 2-stage cp.async; B: register-staged 1 stage. K-chunk 32. 48 KB static.
// ---------------------------------------------------------------------------
template <int K>
__global__ __launch_bounds__(256, 2)
void k_mma_nt_sym(const float* __restrict__ A, size_t sA, int lda,
                  float* __restrict__ D, size_t sD, int ldd) {
    if (blockIdx.x > blockIdx.y) return;   // uniform early exit, before barriers

    __shared__ __align__(128) float smA[8192];    // 2 stages x 128x32 = 32 KB
    __shared__ __align__(128) float smB[4096];    // 1 stage 16 KB (128x32)
    const uint32_t smA_u = smem_u32(smA);
    const uint32_t smB_u = smem_u32(smB);

    const int tid  = threadIdx.x;
    const int lane = tid & 31;
    const int wid  = tid >> 5;
    const int wm   = wid >> 2;
    const int wn   = wid & 3;
    const int gid  = lane >> 2;
    const int tg   = lane & 3;
    const int b    = blockIdx.z;

    const float* Ab = A + (size_t)b * sA + (size_t)blockIdx.y * 128 * lda;
    const float* Bb = A + (size_t)b * sA + (size_t)blockIdx.x * 128 * lda;

    constexpr int NC = K / 32;

    auto load_A = [&](int stg, int c) {
        const int k0 = c * 32;
#pragma unroll
        for (int i = 0; i < 4; i++) {
            int s  = tid + i * 256;
            int r  = s >> 3;
            int ck = s & 7;
            int ph = ck ^ (r & 7);
            uint32_t dst = smA_u + (uint32_t)(stg * 16384 + r * 128 + ph * 16);
            CP_ASYNC16(dst, Ab + (size_t)r * lda + k0 + ck * 4);
        }
        CP_COMMIT();
    };

    float4 breg[4];
    auto ldg_B = [&](int c) {
        const int k0 = c * 32;
#pragma unroll
        for (int i = 0; i < 4; i++) {
            int s = tid + i * 256, r = s >> 3, ck = s & 7;
            breg[i] = *(const float4*)(Bb + (size_t)r * lda + k0 + ck * 4);
        }
    };
    auto store_B = [&]() {
#pragma unroll
        for (int i = 0; i < 4; i++) {
            int s = tid + i * 256, r = s >> 3, ck = s & 7;
            int ph = ck ^ (r & 7);
            *(float4*)((char*)smB + r * 128 + ph * 16) = breg[i];
        }
    };

    float acc[4][4][4];
#pragma unroll
    for (int i = 0; i < 4; i++)
#pragma unroll
        for (int j = 0; j < 4; j++)
#pragma unroll
            for (int t = 0; t < 4; t++) acc[i][j][t] = 0.f;

    const int aRowL = lane & 15;
    const int aQ    = lane >> 4;

    load_A(0, 0);
    ldg_B(0);

    for (int c = 0; c < NC; ++c) {
        __syncthreads();
        if (c + 1 < NC) load_A((c + 1) & 1, c + 1);
        store_B();
        if (c + 1 < NC) ldg_B(c + 1);
        if (c + 1 < NC) CP_WAIT(1); else CP_WAIT(0);
        __syncthreads();

        const uint32_t ApU = smA_u + (uint32_t)((c & 1) * 16384);

#pragma unroll
        for (int p = 0; p < 2; p++) {
            uint32_t bq[4][4];
#pragma unroll
            for (int j = 0; j < 4; j++) {
                int r  = wn * 32 + j * 8 + (lane & 7);
                int ck = p * 4 + (lane >> 3);
                int ph = ck ^ (r & 7);
                ldsm_x4(bq[j][0], bq[j][1], bq[j][2], bq[j][3],
                        smB_u + (uint32_t)(r * 128 + ph * 16));
            }
#pragma unroll
            for (int s2 = 0; s2 < 2; s2++) {
                const int ks = p * 2 + s2;
                uint32_t af[4][4];
#pragma unroll
                for (int i = 0; i < 4; i++) {
                    int r  = wm * 64 + i * 16 + aRowL;
                    int ck = ks * 2 + aQ;
                    int ph = ck ^ (r & 7);
                    ldsm_x4(af[i][0], af[i][1], af[i][2], af[i][3],
                            ApU + (uint32_t)(r * 128 + ph * 16));
                }
#pragma unroll
                for (int i = 0; i < 4; i++)
#pragma unroll
                    for (int j = 0; j < 4; j++)
                        mma_tf32(acc[i][j], af[i][0], af[i][1], af[i][2], af[i][3],
                                 bq[j][s2 * 2 + 0], bq[j][s2 * 2 + 1]);
            }
        }
    }

    // epilogue: normal block
#pragma unroll
    for (int i = 0; i < 4; i++) {
#pragma unroll
        for (int j = 0; j < 4; j++) {
            int row = blockIdx.y * 128 + wm * 64 + i * 16 + gid;
            int col = blockIdx.x * 128 + wn * 32 + j * 8 + tg * 2;
            float* p = D + (size_t)b * sD + (size_t)row * ldd + col;
            *(float2*)p              = make_float2(acc[i][j][0], acc[i][j][1]);
            *(float2*)(p + 8 * ldd)  = make_float2(acc[i][j][2], acc[i][j][3]);
        }
    }
    // epilogue: mirrored block (transposed), off-diagonal only
    if (blockIdx.x != blockIdx.y) {
#pragma unroll
        for (int i = 0; i < 4; i++) {
#pragma unroll
            for (int j = 0; j < 4; j++) {
                int row0 = blockIdx.y * 128 + wm * 64 + i * 16 + gid;
                int col0 = blockIdx.x * 128 + wn * 32 + j * 8 + tg * 2;
                float* q = D + (size_t)b * sD;
                q[(size_t)(col0    ) * ldd + row0    ] = acc[i][j][0];
                q[(size_t)(col0 + 1) * ldd + row0    ] = acc[i][j][1];
                q[(size_t)(col0    ) * ldd + row0 + 8] = acc[i][j][2];
                q[(size_t)(col0 + 1) * ldd + row0 + 8] = acc[i][j][3];
            }
        }
    }
}

// ---------------------------------------------------------------------------
// Kernel 3: fused exp-GEMM + softmax normalization.
//   O[m][n] = ( sum_k exp(S[m][k]) * X[k][n] ) / ( sum_k exp(S[m][k]) )
// Cosine scores are bounded in [-1,1] -> exp never overflows; no max pass.
// A = raw S: register-staged, transformed tf32(expf(.)) during STS, with
// per-row sum accumulated in registers (each CTA streams FULL P rows).
// B = xc: 2-stage cp.async. K-chunk 32. smem = 16 + 32 = 48 KB static.
// ---------------------------------------------------------------------------
__global__ __launch_bounds__(256, 2)
void k_mma_pv(const float* __restrict__ S, size_t sS,
              const float* __restrict__ X, size_t sX,
              float* __restrict__ O, size_t sO) {
    __shared__ __align__(128) float smA[4096];    // 1 stage 128x32 = 16 KB (then rowsum scratch)
    __shared__ __align__(128) float smB[8192];    // 2 stages x 32x128 = 32 KB
    const uint32_t smA_u = smem_u32(smA);
    const int tid  = threadIdx.x;
    const int lane = tid & 31;
    const int wid  = tid >> 5;
    const int wm   = wid >> 2;
    const int wn   = wid & 3;
    const int gid  = lane >> 2;
    const int tg   = lane & 3;
    const int b    = blockIdx.z;

    const float* Ab = S + (size_t)b * sS + (size_t)blockIdx.y * 128 * SEQ;
    const float* Bb = X + (size_t)b * sX + (size_t)blockIdx.x * 128;

    constexpr int NC = SEQ / 32;   // 64

    // ---- B: cp.async 2-stage, rotate swizzle within 128B groups ----
    auto load_B = [&](int stg, int c) {
        const int k0 = c * 32;
#pragma unroll
        for (int i = 0; i < 4; i++) {
            int s  = tid + i * 256;
            int r  = s >> 5;                 // k-row 0..31
            int ck = s & 31;                 // 16B chunk along n (0..31)
            int ph = (ck & ~7) | ((ck + 2 * (r & 3)) & 7);
            uint32_t dst = smem_u32(smB) + (uint32_t)(stg * 16384 + r * 512 + ph * 16);
            CP_ASYNC16(dst, Bb + (size_t)(k0 + r) * DIM + ck * 4);
        }
        CP_COMMIT();
    };

    // ---- A: register-staged raw scores; exp + tf32 + rowsum at store ----
    float4 areg[4];
    float  psum[4] = {0.f, 0.f, 0.f, 0.f};
    auto ldg_A = [&](int c) {
        const int k0 = c * 32;
#pragma unroll
        for (int i = 0; i < 4; i++) {
            int s = tid + i * 256, r = s >> 3, ck = s & 7;
            areg[i] = *(const float4*)(Ab + (size_t)r * SEQ + k0 + ck * 4);
        }
    };
    auto store_A = [&]() {
#pragma unroll
        for (int i = 0; i < 4; i++) {
            int s = tid + i * 256, r = s >> 3, ck = s & 7;
            int ph = ck ^ (r & 7);
            float4 e;
            e.x = to_tf32(__expf(areg[i].x));
            e.y = to_tf32(__expf(areg[i].y));
            e.z = to_tf32(__expf(areg[i].z));
            e.w = to_tf32(__expf(areg[i].w));
            psum[i] += (e.x + e.y) + (e.z + e.w);
            *(float4*)((char*)smA + r * 128 + ph * 16) = e;
        }
    };

    float acc[4][4][4];
#pragma unroll
    for (int i = 0; i < 4; i++)
#pragma unroll
        for (int j = 0; j < 4; j++)
#pragma unroll
            for (int t = 0; t < 4; t++) acc[i][j][t] = 0.f;

    const int aRowL = lane & 15;
    const int aQ    = lane >> 4;

    load_B(0, 0);
    ldg_A(0);

    for (int c = 0; c < NC; ++c) {
        __syncthreads();                        // compute(c-1) done: smA + B stage (c+1)&1 free
        if (c + 1 < NC) load_B((c + 1) & 1, c + 1);
        store_A();
        if (c + 1 < NC) ldg_A(c + 1);
        if (c + 1 < NC) CP_WAIT(1); else CP_WAIT(0);   // B(c) complete
        __syncthreads();                        // A(c) + B(c) visible

        const float* Bp = smB + (c & 1) * 4096;

#pragma unroll
        for (int ks = 0; ks < 4; ks++) {
            uint32_t af[4][4];
#pragma unroll
            for (int i = 0; i < 4; i++) {
                int r  = wm * 64 + i * 16 + aRowL;
                int ck = ks * 2 + aQ;
                int ph = ck ^ (r & 7);
                ldsm_x4(af[i][0], af[i][1], af[i][2], af[i][3],
                        smA_u + (uint32_t)(r * 128 + ph * 16));
            }
            uint32_t bf[4][2];
#pragma unroll
            for (int j = 0; j < 4; j++) {
                int col = wn * 32 + j * 8 + gid;
                int kk  = ks * 8 + tg;
                int ck  = col >> 2;
                int ph  = (ck & ~7) | ((ck + 2 * (kk & 3)) & 7);
                const char* base = (const char*)Bp + ph * 16 + (col & 3) * 4;
                bf[j][0] = *(const uint32_t*)(base + kk * 512);
                bf[j][1] = *(const uint32_t*)(base + (kk + 4) * 512);
            }
#pragma unroll
            for (int i = 0; i < 4; i++)
#pragma unroll
                for (int j = 0; j < 4; j++)
                    mma_tf32(acc[i][j], af[i][0], af[i][1], af[i][2], af[i][3],
                             bf[j][0], bf[j][1]);
        }
    }

    // ---- rowsum reduction: partials -> smA (reused as scratch) ----
    __syncthreads();                            // last compute done reading smA
    {
        // thread t holds rows (t>>3)+32i covering col-chunk (t&7)
#pragma unroll
        for (int i = 0; i < 4; i++) {
            int r = (tid >> 3) + 32 * i;
            smA[r * 8 + (tid & 7)] = psum[i];
        }
    }
    __syncthreads();
    if (tid < 128) {
        float s = 0.f;
#pragma unroll
        for (int u = 0; u < 8; u++) s += smA[tid * 8 + u];
        smA[1024 + tid] = 1.f / s;
    }
    __syncthreads();

    // ---- epilogue: O = acc * (1/rowsum) ----
#pragma unroll
    for (int i = 0; i < 4; i++) {
#pragma unroll
        for (int j = 0; j < 4; j++) {
            int rl0 = wm * 64 + i * 16 + gid;
            float inv0 = smA[1024 + rl0];
            float inv1 = smA[1024 + rl0 + 8];
            int row = blockIdx.y * 128 + rl0;
            int col = blockIdx.x * 128 + wn * 32 + j * 8 + tg * 2;
            float* p = O + (size_t)b * sO + (size_t)row * DIM + col;
            *(float2*)p             = make_float2(acc[i][j][0] * inv0, acc[i][j][1] * inv0);
            *(float2*)(p + 8 * DIM) = make_float2(acc[i][j][2] * inv1, acc[i][j][3] * inv1);
        }
    }
}

// ---------------------------------------------------------------------------
extern "C" void kernel_launch(void* const* d_in, const int* in_sizes, int n_in,
                              void* d_out, int out_size) {
    const float* x = (const float*)d_in[0];
    float* out = (float*)d_out;

    float *scores, *xn, *xc;
    cudaGetSymbolAddress((void**)&scores, g_scores);
    cudaGetSymbolAddress((void**)&xn, g_xn);
    cudaGetSymbolAddress((void**)&xc, g_xc);

    // 1) normalize + tf32-round both operand copies
    k_norm<<<BATCH * SEQ, 128>>>(x, xn, xc);

    // 2) S = xn . xn^T   (NT, K = 512, symmetric: lower-triangle blocks only)
    k_mma_nt_sym<DIM><<<dim3(SEQ / 128, SEQ / 128, BATCH), 256>>>(
        xn, (size_t)SEQ * DIM, DIM,
        scores, (size_t)SEQ * SEQ, SEQ);

    // 3) O = softmax(S) . X, fused: exp+rowsum inside the GEMM (bounded scores)
    k_mma_pv<<<dim3(DIM / 128, SEQ / 128, BATCH), 256>>>(
        scores, (size_t)SEQ * SEQ,
        xc, (size_t)SEQ * DIM,
        out, (size_t)SEQ * DIM);
}

// round 14
// speedup vs baseline: 8.6378x; 1.8365x over previous
#include <cuda_runtime.h>
#include <cuda_fp16.h>
#include <cstdint>

#define BATCH 16
#define SEQ   2048
#define DIM   512

// ---------------------------------------------------------------------------
// Scratch (device globals = sanctioned no-alloc scratch)
// ---------------------------------------------------------------------------
__device__ __half g_p [(size_t)BATCH * SEQ * SEQ];   // 134 MB: P = exp(S), fp16
__device__ __half g_xn[(size_t)BATCH * SEQ * DIM];   // normalized x, fp16
__device__ __half g_xc[(size_t)BATCH * SEQ * DIM];   // raw x, fp16

// ---------------------------------------------------------------------------
// Helpers (baseline PTX, sm_75+/sm_80+ -- safe for compute_103 target)
// ---------------------------------------------------------------------------
__device__ __forceinline__ uint32_t smem_u32(const void* p) {
    uint32_t a;
    asm("{ .reg .u64 t; cvta.to.shared.u64 t, %1; cvt.u32.u64 %0, t; }" : "=r"(a) : "l"(p));
    return a;
}
#define CP_ASYNC16(dst, src) \
    asm volatile("cp.async.cg.shared.global [%0], [%1], 16;" :: "r"(dst), "l"(src))
#define CP_COMMIT() asm volatile("cp.async.commit_group;" ::: "memory")
#define CP_WAIT(n)  asm volatile("cp.async.wait_group %0;" :: "n"(n) : "memory")

__device__ __forceinline__ void ldsm_x4(uint32_t& r0, uint32_t& r1, uint32_t& r2, uint32_t& r3,
                                        uint32_t addr) {
    asm volatile("ldmatrix.sync.aligned.m8n8.x4.shared.b16 {%0,%1,%2,%3}, [%4];"
                 : "=r"(r0), "=r"(r1), "=r"(r2), "=r"(r3) : "r"(addr));
}
__device__ __forceinline__ void ldsm_x4_t(uint32_t& r0, uint32_t& r1, uint32_t& r2, uint32_t& r3,
                                          uint32_t addr) {
    asm volatile("ldmatrix.sync.aligned.m8n8.x4.trans.shared.b16 {%0,%1,%2,%3}, [%4];"
                 : "=r"(r0), "=r"(r1), "=r"(r2), "=r"(r3) : "r"(addr));
}

__device__ __forceinline__ void mma_f16(float* c,
                                        uint32_t a0, uint32_t a1, uint32_t a2, uint32_t a3,
                                        uint32_t b0, uint32_t b1) {
    asm volatile(
        "mma.sync.aligned.m16n8k16.row.col.f32.f16.f16.f32 "
        "{%0,%1,%2,%3}, {%4,%5,%6,%7}, {%8,%9}, {%0,%1,%2,%3};"
        : "+f"(c[0]), "+f"(c[1]), "+f"(c[2]), "+f"(c[3])
        : "r"(a0), "r"(a1), "r"(a2), "r"(a3), "r"(b0), "r"(b1));
}

// ---------------------------------------------------------------------------
// Kernel 1: row L2-normalize; write xn = h(x/|x|) and xc = h(x), fp16.
// ---------------------------------------------------------------------------
__global__ __launch_bounds__(128)
void k_norm(const float* __restrict__ x, __half* __restrict__ xn, __half* __restrict__ xc) {
    const size_t row = blockIdx.x;
    const int tid = threadIdx.x;
    float4 v = *(const float4*)(x + row * DIM + tid * 4);
    float s = v.x * v.x + v.y * v.y + v.z * v.z + v.w * v.w;
#pragma unroll
    for (int o = 16; o > 0; o >>= 1) s += __shfl_xor_sync(0xffffffffu, s, o);
    __shared__ float red[4];
    if ((tid & 31) == 0) red[tid >> 5] = s;
    __syncthreads();
    float inv = rsqrtf(red[0] + red[1] + red[2] + red[3]);
    __half2 n0 = __floats2half2_rn(v.x * inv, v.y * inv);
    __half2 n1 = __floats2half2_rn(v.z * inv, v.w * inv);
    __half2 c0 = __floats2half2_rn(v.x, v.y);
    __half2 c1 = __floats2half2_rn(v.z, v.w);
    *(__half2*)(xn + row * DIM + tid * 4)     = n0;
    *(__half2*)(xn + row * DIM + tid * 4 + 2) = n1;
    *(__half2*)(xc + row * DIM + tid * 4)     = c0;
    *(__half2*)(xc + row * DIM + tid * 4 + 2) = c1;
}

// ---------------------------------------------------------------------------
// Kernel 2: GEMM1 (fp16 NT, symmetric): P = exp(xn . xn^T), stored fp16.
// Block 128x128, K-chunk 64 halves (128B rows), XOR-16B swizzle.
// A: 2-stage cp.async (16 KB each); B: 1 stage register-staged (16 KB).
// Epilogue applies exp (scores bounded in [-1,1] -> safe) and writes
// the mirrored transposed block for off-diagonal tiles. 48 KB static smem.
// ---------------------------------------------------------------------------
template <int K>
__global__ __launch_bounds__(256, 2)
void k_mma_nt_sym(const __half* __restrict__ A, size_t sA, int lda,
                  __half* __restrict__ P, size_t sD, int ldd) {
    if (blockIdx.x > blockIdx.y) return;   // uniform early exit, before barriers

    __shared__ __align__(128) float smA[8192];    // 2 stages x 128rows x 128B = 32 KB
    __shared__ __align__(128) float smB[4096];    // 1 stage 16 KB
    const uint32_t smA_u = smem_u32(smA);
    const uint32_t smB_u = smem_u32(smB);

    const int tid  = threadIdx.x;
    const int lane = tid & 31;
    const int wid  = tid >> 5;
    const int wm   = wid >> 2;
    const int wn   = wid & 3;
    const int gid  = lane >> 2;
    const int tg   = lane & 3;
    const int b    = blockIdx.z;

    const __half* Ab = A + (size_t)b * sA + (size_t)blockIdx.y * 128 * lda;
    const __half* Bb = A + (size_t)b * sA + (size_t)blockIdx.x * 128 * lda;

    constexpr int NC = K / 64;

    auto load_A = [&](int stg, int c) {
        const int k0 = c * 64;
#pragma unroll
        for (int i = 0; i < 4; i++) {
            int s  = tid + i * 256;          // 16B chunk id (0..1023)
            int r  = s >> 3;                 // row 0..127
            int ck = s & 7;                  // chunk within 128B row
            int ph = ck ^ (r & 7);
            uint32_t dst = smA_u + (uint32_t)(stg * 16384 + r * 128 + ph * 16);
            CP_ASYNC16(dst, Ab + (size_t)r * lda + k0 + ck * 8);
        }
        CP_COMMIT();
    };

    uint4 breg[4];
    auto ldg_B = [&](int c) {
        const int k0 = c * 64;
#pragma unroll
        for (int i = 0; i < 4; i++) {
            int s = tid + i * 256, r = s >> 3, ck = s & 7;
            breg[i] = *(const uint4*)(Bb + (size_t)r * lda + k0 + ck * 8);
        }
    };
    auto store_B = [&]() {
#pragma unroll
        for (int i = 0; i < 4; i++) {
            int s = tid + i * 256, r = s >> 3, ck = s & 7;
            int ph = ck ^ (r & 7);
            *(uint4*)((char*)smB + r * 128 + ph * 16) = breg[i];
        }
    };

    float acc[4][4][4];
#pragma unroll
    for (int i = 0; i < 4; i++)
#pragma unroll
        for (int j = 0; j < 4; j++)
#pragma unroll
            for (int t = 0; t < 4; t++) acc[i][j][t] = 0.f;

    load_A(0, 0);
    ldg_B(0);

    for (int c = 0; c < NC; ++c) {
        __syncthreads();
        if (c + 1 < NC) load_A((c + 1) & 1, c + 1);
        store_B();
        if (c + 1 < NC) ldg_B(c + 1);
        if (c + 1 < NC) CP_WAIT(1); else CP_WAIT(0);
        __syncthreads();

        const uint32_t ApU = smA_u + (uint32_t)((c & 1) * 16384);

#pragma unroll
        for (int ks = 0; ks < 4; ks++) {           // k16 steps within chunk 64
            uint32_t af[4][4];
#pragma unroll
            for (int i = 0; i < 4; i++) {
                int r  = wm * 64 + i * 16 + (lane & 15);
                int ck = ks * 2 + (lane >> 4);
                int ph = ck ^ (r & 7);
                ldsm_x4(af[i][0], af[i][1], af[i][2], af[i][3],
                        ApU + (uint32_t)(r * 128 + ph * 16));
            }
#pragma unroll
            for (int jp = 0; jp < 2; jp++) {       // two j-tiles per x4
                uint32_t bq0, bq1, bq2, bq3;
                int r  = wn * 32 + jp * 16 + ((lane >> 4) << 3) + (lane & 7);
                int ck = ks * 2 + ((lane >> 3) & 1);
                int ph = ck ^ (r & 7);
                ldsm_x4(bq0, bq1, bq2, bq3, smB_u + (uint32_t)(r * 128 + ph * 16));
#pragma unroll
                for (int i = 0; i < 4; i++) {
                    mma_f16(acc[i][jp * 2 + 0], af[i][0], af[i][1], af[i][2], af[i][3], bq0, bq1);
                    mma_f16(acc[i][jp * 2 + 1], af[i][0], af[i][1], af[i][2], af[i][3], bq2, bq3);
                }
            }
        }
    }

    // epilogue: exp + fp16 store; mirror transposed for off-diagonal blocks
    const bool mirror = (blockIdx.x != blockIdx.y);
    __half* Pb = P + (size_t)b * sD;
#pragma unroll
    for (int i = 0; i < 4; i++) {
#pragma unroll
        for (int j = 0; j < 4; j++) {
            int row = blockIdx.y * 128 + wm * 64 + i * 16 + gid;
            int col = blockIdx.x * 128 + wn * 32 + j * 8 + tg * 2;
            float e0 = __expf(acc[i][j][0]);
            float e1 = __expf(acc[i][j][1]);
            float e2 = __expf(acc[i][j][2]);
            float e3 = __expf(acc[i][j][3]);
            *(__half2*)(Pb + (size_t)row * ldd + col)       = __floats2half2_rn(e0, e1);
            *(__half2*)(Pb + (size_t)(row + 8) * ldd + col) = __floats2half2_rn(e2, e3);
            if (mirror) {
                Pb[(size_t)(col    ) * ldd + row    ] = __float2half_rn(e0);
                Pb[(size_t)(col + 1) * ldd + row    ] = __float2half_rn(e1);
                Pb[(size_t)(col    ) * ldd + row + 8] = __float2half_rn(e2);
                Pb[(size_t)(col + 1) * ldd + row + 8] = __float2half_rn(e3);
            }
        }
    }
}

// ---------------------------------------------------------------------------
// Kernel 3: fused PV (fp16 NN): O[m][n] = (sum_k P[m][k] X[k][n]) / sum_k P[m][k]
// A = P fp16: register-staged 1 stage (16 KB), per-row sums accumulated
// during staging (plain adds -- exp already applied in GEMM1).
// B = xc fp16 [k][n]: 2-stage cp.async (16 KB each), (ck+r)&15 swizzle,
// fragments via ldmatrix.trans. K-chunk 64. 48 KB static smem.
// ---------------------------------------------------------------------------
__global__ __launch_bounds__(256, 2)
void k_mma_pv(const __half* __restrict__ P, size_t sS,
              const __half* __restrict__ X, size_t sX,
              float* __restrict__ O, size_t sO) {
    __shared__ __align__(128) float smA[4096];    // 1 stage 16 KB (later rowsum scratch)
    __shared__ __align__(128) float smB[8192];    // 2 stages x 64rows x 256B = 32 KB
    const uint32_t smA_u = smem_u32(smA);
    const uint32_t smB_u = smem_u32(smB);

    const int tid  = threadIdx.x;
    const int lane = tid & 31;
    const int wid  = tid >> 5;
    const int wm   = wid >> 2;
    const int wn   = wid & 3;
    const int gid  = lane >> 2;
    const int tg   = tid & 3;      // (unused for B now; kept for epilogue col calc)
    const int b    = blockIdx.z;

    const __half* Ab = P + (size_t)b * sS + (size_t)blockIdx.y * 128 * SEQ;
    const __half* Bb = X + (size_t)b * sX + (size_t)blockIdx.x * 128;

    constexpr int NC = SEQ / 64;   // 32

    auto load_B = [&](int stg, int c) {
        const int k0 = c * 64;
#pragma unroll
        for (int i = 0; i < 4; i++) {
            int s  = tid + i * 256;          // 16B chunk id (0..1023)
            int r  = s >> 4;                 // k-row 0..63
            int ck = s & 15;                 // chunk along n (256B row)
            int ph = (ck + r) & 15;
            uint32_t dst = smB_u + (uint32_t)(stg * 16384 + r * 256 + ph * 16);
            CP_ASYNC16(dst, Bb + (size_t)(k0 + r) * DIM + ck * 8);
        }
        CP_COMMIT();
    };

    uint4 areg[4];
    float psum[4] = {0.f, 0.f, 0.f, 0.f};
    auto ldg_A = [&](int c) {
        const int k0 = c * 64;
#pragma unroll
        for (int i = 0; i < 4; i++) {
            int s = tid + i * 256, r = s >> 3, ck = s & 7;
            areg[i] = *(const uint4*)(Ab + (size_t)r * SEQ + k0 + ck * 8);
        }
    };
    auto store_A = [&]() {
#pragma unroll
        for (int i = 0; i < 4; i++) {
            int s = tid + i * 256, r = s >> 3, ck = s & 7;
            int ph = ck ^ (r & 7);
            // rowsum: 8 halves of row r
            const __half2* h = (const __half2*)&areg[i];
            float2 f0 = __half22float2(h[0]);
            float2 f1 = __half22float2(h[1]);
            float2 f2 = __half22float2(h[2]);
            float2 f3 = __half22float2(h[3]);
            psum[i] += ((f0.x + f0.y) + (f1.x + f1.y)) + ((f2.x + f2.y) + (f3.x + f3.y));
            *(uint4*)((char*)smA + r * 128 + ph * 16) = areg[i];
        }
    };

    float acc[4][4][4];
#pragma unroll
    for (int i = 0; i < 4; i++)
#pragma unroll
        for (int j = 0; j < 4; j++)
#pragma unroll
            for (int t = 0; t < 4; t++) acc[i][j][t] = 0.f;

    load_B(0, 0);
    ldg_A(0);

    for (int c = 0; c < NC; ++c) {
        __syncthreads();                       // compute(c-1) done: smA + B stage free
        if (c + 1 < NC) load_B((c + 1) & 1, c + 1);
        store_A();
        if (c + 1 < NC) ldg_A(c + 1);
        if (c + 1 < NC) CP_WAIT(1); else CP_WAIT(0);
        __syncthreads();                       // A(c) + B(c) visible

        const uint32_t BpU = smB_u + (uint32_t)((c & 1) * 16384);

#pragma unroll
        for (int ks = 0; ks < 4; ks++) {
            uint32_t af[4][4];
#pragma unroll
            for (int i = 0; i < 4; i++) {
                int r  = wm * 64 + i * 16 + (lane & 15);
                int ck = ks * 2 + (lane >> 4);
                int ph = ck ^ (r & 7);
                ldsm_x4(af[i][0], af[i][1], af[i][2], af[i][3],
                        smA_u + (uint32_t)(r * 128 + ph * 16));
            }
#pragma unroll
            for (int jp = 0; jp < 2; jp++) {
                uint32_t bq0, bq1, bq2, bq3;
                int r  = ks * 16 + ((lane >> 3) & 1) * 8 + (lane & 7);
                int ck = wn * 4 + jp * 2 + (lane >> 4);
                int ph = (ck + r) & 15;
                ldsm_x4_t(bq0, bq1, bq2, bq3, BpU + (uint32_t)(r * 256 + ph * 16));
#pragma unroll
                for (int i = 0; i < 4; i++) {
                    mma_f16(acc[i][jp * 2 + 0], af[i][0], af[i][1], af[i][2], af[i][3], bq0, bq1);
                    mma_f16(acc[i][jp * 2 + 1], af[i][0], af[i][1], af[i][2], af[i][3], bq2, bq3);
                }
            }
        }
    }

    // ---- rowsum reduction via smA (reused as float scratch) ----
    __syncthreads();
    {
#pragma unroll
        for (int i = 0; i < 4; i++) {
            int r = (tid >> 3) + 32 * i;
            smA[r * 8 + (tid & 7)] = psum[i];
        }
    }
    __syncthreads();
    if (tid < 128) {
        float s = 0.f;
#pragma unroll
        for (int u = 0; u < 8; u++) s += smA[tid * 8 + u];
        smA[1024 + tid] = 1.f / s;
    }
    __syncthreads();

    // ---- epilogue: O = acc * (1/rowsum) ----
#pragma unroll
    for (int i = 0; i < 4; i++) {
#pragma unroll
        for (int j = 0; j < 4; j++) {
            int rl0 = wm * 64 + i * 16 + gid;
            float inv0 = smA[1024 + rl0];
            float inv1 = smA[1024 + rl0 + 8];
            int row = blockIdx.y * 128 + rl0;
            int col = blockIdx.x * 128 + wn * 32 + j * 8 + (lane & 3) * 2;
            float* p = O + (size_t)b * sO + (size_t)row * DIM + col;
            *(float2*)p             = make_float2(acc[i][j][0] * inv0, acc[i][j][1] * inv0);
            *(float2*)(p + 8 * DIM) = make_float2(acc[i][j][2] * inv1, acc[i][j][3] * inv1);
        }
    }
}

// ---------------------------------------------------------------------------
extern "C" void kernel_launch(void* const* d_in, const int* in_sizes, int n_in,
                              void* d_out, int out_size) {
    const float* x = (const float*)d_in[0];
    float* out = (float*)d_out;

    __half *pm, *xn, *xc;
    cudaGetSymbolAddress((void**)&pm, g_p);
    cudaGetSymbolAddress((void**)&xn, g_xn);
    cudaGetSymbolAddress((void**)&xc, g_xc);

    // 1) normalize + fp16 conversions
    k_norm<<<BATCH * SEQ, 128>>>(x, xn, xc);

    // 2) P = exp(xn . xn^T)  (fp16 NT, symmetric: lower-triangle blocks only)
    k_mma_nt_sym<DIM><<<dim3(SEQ / 128, SEQ / 128, BATCH), 256>>>(
        xn, (size_t)SEQ * DIM, DIM,
        pm, (size_t)SEQ * SEQ, SEQ);

    // 3) O = (P . X) / rowsum(P)  (fp16 NN, fused normalization)
    k_mma_pv<<<dim3(DIM / 128, SEQ / 128, BATCH), 256>>>(
        pm, (size_t)SEQ * SEQ,
        xc, (size_t)SEQ * DIM,
        out, (size_t)SEQ * DIM);
}